// round 8
// baseline (speedup 1.0000x reference)
#include <cuda_runtime.h>
#include <cuda_bf16.h>
#include <cuda_fp16.h>
#include <cuda_fp8.h>
#include <stdint.h>
#include <math.h>

// Problem constants
#define Bb   2
#define SS   2048
#define DD   2048
#define HH   16
#define HD   128
#define MTOT 4096   // Bb*SS
#define KK   2048

// ---------------------------------------------------------------------------
// Scratch (device globals: allocation-free rule)
// ---------------------------------------------------------------------------
__device__ __half  g_x16[(size_t)MTOT * DD];
__device__ uint8_t g_x8h[(size_t)MTOT * DD];
__device__ uint8_t g_x8l[(size_t)MTOT * DD];
__device__ __half  g_w16[(size_t)4 * DD * DD];   // Wq,Wk,Wv,Wo
__device__ uint8_t g_w8h[(size_t)4 * DD * DD];
__device__ uint8_t g_w8l[(size_t)4 * DD * DD];
__device__ __nv_bfloat16 g_qhi[(size_t)Bb * HH * SS * HD];  // [b,h,s,hd]
__device__ __nv_bfloat16 g_qlo[(size_t)Bb * HH * SS * HD];
__device__ __nv_bfloat16 g_khi[(size_t)Bb * HH * SS * HD];
__device__ __nv_bfloat16 g_klo[(size_t)Bb * HH * SS * HD];
__device__ __nv_bfloat16 g_vhi[(size_t)Bb * HH * SS * HD];
__device__ __nv_bfloat16 g_vlo[(size_t)Bb * HH * SS * HD];
__device__ __half  g_a16[(size_t)MTOT * DD];     // attn out [b,s,d]
__device__ uint8_t g_a8h[(size_t)MTOT * DD];
__device__ uint8_t g_a8l[(size_t)MTOT * DD];

// Scales: cross accumulator carries 2^18; hi side *64 (2^6), lo side *4096 (2^12)
#define SC_HI     64.0f
#define SC_LO     4096.0f
#define SC_INV    3.814697265625e-06f   // 2^-18

// ---------------------------------------------------------------------------
// PTX helpers (family-safe)
// ---------------------------------------------------------------------------
__device__ __forceinline__ uint32_t smem_to_u32(const void* p) {
    uint32_t a;
    asm("{ .reg .u64 t; cvta.to.shared.u64 t, %1; cvt.u32.u64 %0, t; }"
        : "=r"(a) : "l"(p));
    return a;
}

__device__ __forceinline__ void cp_async16(uint32_t saddr, const void* gaddr) {
    asm volatile("cp.async.cg.shared.global [%0], [%1], 16;"
                 :: "r"(saddr), "l"(gaddr) : "memory");
}
#define CP_COMMIT() asm volatile("cp.async.commit_group;" ::: "memory")
#define CP_WAIT1()  asm volatile("cp.async.wait_group 1;" ::: "memory")
#define CP_WAIT2()  asm volatile("cp.async.wait_group 2;" ::: "memory")

#define LDSM4(r0, r1, r2, r3, addr) \
    asm volatile("ldmatrix.sync.aligned.m8n8.x4.shared.b16 {%0,%1,%2,%3}, [%4];" \
                 : "=r"(r0), "=r"(r1), "=r"(r2), "=r"(r3) : "r"(addr))

#define LDSM4T(r0, r1, r2, r3, addr) \
    asm volatile("ldmatrix.sync.aligned.m8n8.x4.trans.shared.b16 {%0,%1,%2,%3}, [%4];" \
                 : "=r"(r0), "=r"(r1), "=r"(r2), "=r"(r3) : "r"(addr))

#define MMA16816(d, a, b) \
    asm volatile("mma.sync.aligned.m16n8k16.row.col.f32.bf16.bf16.f32 " \
                 "{%0,%1,%2,%3}, {%4,%5,%6,%7}, {%8,%9}, {%0,%1,%2,%3};" \
                 : "+f"((d)[0]), "+f"((d)[1]), "+f"((d)[2]), "+f"((d)[3]) \
                 : "r"((a)[0]), "r"((a)[1]), "r"((a)[2]), "r"((a)[3]), \
                   "r"((b)[0]), "r"((b)[1]))

#define MMAF16(d, a, b) \
    asm volatile("mma.sync.aligned.m16n8k16.row.col.f32.f16.f16.f32 " \
                 "{%0,%1,%2,%3}, {%4,%5,%6,%7}, {%8,%9}, {%0,%1,%2,%3};" \
                 : "+f"((d)[0]), "+f"((d)[1]), "+f"((d)[2]), "+f"((d)[3]) \
                 : "r"((a)[0]), "r"((a)[1]), "r"((a)[2]), "r"((a)[3]), \
                   "r"((b)[0]), "r"((b)[1]))

#define MMAF8(d, a, b) \
    asm volatile("mma.sync.aligned.m16n8k32.row.col.f32.e4m3.e4m3.f32 " \
                 "{%0,%1,%2,%3}, {%4,%5,%6,%7}, {%8,%9}, {%0,%1,%2,%3};" \
                 : "+f"((d)[0]), "+f"((d)[1]), "+f"((d)[2]), "+f"((d)[3]) \
                 : "r"((a)[0]), "r"((a)[1]), "r"((a)[2]), "r"((a)[3]), \
                   "r"((b)[0]), "r"((b)[1]))

__device__ __forceinline__ uint32_t packbf(float x, float y) {
    __nv_bfloat162 t = __floats2bfloat162_rn(x, y);
    return *(uint32_t*)&t;
}
__device__ __forceinline__ uint32_t packh2(__half a, __half b) {
    __half2 t = __halves2half2(a, b);
    return *(uint32_t*)&t;
}
__device__ __forceinline__ uint8_t f2e4m3(float f) {
    return (uint8_t)__nv_cvt_float_to_fp8(f, __NV_SATFINITE, __NV_E4M3);
}

// ---------------------------------------------------------------------------
// Fused split: x and all 4 weights -> fp16 hi + fp8(hi*64) + fp8(lo*4096).
// blockIdx.y: 0 -> x, 1..4 -> W[y-1].
// ---------------------------------------------------------------------------
__global__ __launch_bounds__(256) void split_all_kernel(
    const float* __restrict__ x,  const float* __restrict__ Wq,
    const float* __restrict__ Wk, const float* __restrict__ Wv,
    const float* __restrict__ Wo,
    __half* __restrict__ x16, uint8_t* __restrict__ x8h, uint8_t* __restrict__ x8l,
    __half* __restrict__ w16, uint8_t* __restrict__ w8h, uint8_t* __restrict__ w8l,
    int xn4, int wn4)
{
    const int y = blockIdx.y;
    const float* in;
    __half* h16; uint8_t *h8h, *h8l;
    int n4;
    if (y == 0) { in = x; h16 = x16; h8h = x8h; h8l = x8l; n4 = xn4; }
    else {
        const float* ws[4] = {Wq, Wk, Wv, Wo};
        in = ws[y - 1];
        const size_t off = (size_t)(y - 1) * DD * DD;
        h16 = w16 + off; h8h = w8h + off; h8l = w8l + off; n4 = wn4;
    }
    int i = blockIdx.x * blockDim.x + threadIdx.x;
    if (i >= n4) return;
    float4 v = ((const float4*)in)[i];
    __half p0 = __float2half(v.x), p1 = __float2half(v.y);
    __half p2 = __float2half(v.z), p3 = __float2half(v.w);
    float f0 = __half2float(p0), f1 = __half2float(p1);
    float f2 = __half2float(p2), f3 = __half2float(p3);
    ((uint32_t*)h16)[2 * i + 0] = packh2(p0, p1);
    ((uint32_t*)h16)[2 * i + 1] = packh2(p2, p3);
    uint32_t b8h = (uint32_t)f2e4m3(f0 * SC_HI)
                 | ((uint32_t)f2e4m3(f1 * SC_HI) << 8)
                 | ((uint32_t)f2e4m3(f2 * SC_HI) << 16)
                 | ((uint32_t)f2e4m3(f3 * SC_HI) << 24);
    uint32_t b8l = (uint32_t)f2e4m3((v.x - f0) * SC_LO)
                 | ((uint32_t)f2e4m3((v.y - f1) * SC_LO) << 8)
                 | ((uint32_t)f2e4m3((v.z - f2) * SC_LO) << 16)
                 | ((uint32_t)f2e4m3((v.w - f3) * SC_LO) << 24);
    ((uint32_t*)h8h)[i] = b8h;
    ((uint32_t*)h8l)[i] = b8l;
}

// ---------------------------------------------------------------------------
// GEMM:  Y[m,n] = sum_k X[m,k] * W[n,k]
//   term A: xh(fp16) * wh(fp16)     1x mma16816.f16 per k16
//   term B: fp8 concat cross-term   1x mma16832.e4m3 per k32 (covers both
//           xh*wl and xl*wh, result scaled 2^18)
// 512 threads / 16 warps, warp tile 32x32, 4-stage cp.async, CTA 128x128.
// SMEM stage tiles (pitch 80B, 64B data rows):
//   T0 Xh fp16 | T1 [x8h|x8l] | T2 Wh fp16 | T3 [w8l|w8h]
// ---------------------------------------------------------------------------
#define TPITCHB  80
#define TILEB    10240         // 128 * 80
#define STAGEB   40960
#define NSTAGE   4
#define GSMEM_TOTAL (NSTAGE * STAGEB)
#define NCHUNK   (KK / 32)

__global__ __launch_bounds__(512, 1) void gemm_hmma(
    const __half* __restrict__ X16,
    const uint8_t* __restrict__ X8h, const uint8_t* __restrict__ X8l,
    const __half* __restrict__ W16Base,
    const uint8_t* __restrict__ W8hBase, const uint8_t* __restrict__ W8lBase,
    float* __restrict__ Yf,
    __nv_bfloat16* __restrict__ Y0hi, __nv_bfloat16* __restrict__ Y0lo,
    __nv_bfloat16* __restrict__ Y1hi, __nv_bfloat16* __restrict__ Y1lo,
    __nv_bfloat16* __restrict__ Y2hi, __nv_bfloat16* __restrict__ Y2lo,
    int qkv)
{
    extern __shared__ char smem[];
    const uint32_t sb = smem_to_u32(smem);

    const int tid  = threadIdx.x;
    const int wid  = tid >> 5;
    const int lane = tid & 31;
    const int wm   = wid >> 2;    // 0..3
    const int wn   = wid & 3;     // 0..3
    const int m0   = blockIdx.y * 128;
    const int n0   = blockIdx.x * 128;
    const int z    = blockIdx.z;

    const __half*  W16 = W16Base + (size_t)z * DD * DD;
    const uint8_t* W8h = W8hBase + (size_t)z * DD * DD;
    const uint8_t* W8l = W8lBase + (size_t)z * DD * DD;

    const int ltile = tid >> 7;         // 0:Xh 1:X8 2:Wh 3:W8
    const int lwi   = tid & 127;
    const uint32_t stile = sb + ltile * TILEB;

    auto load_stage = [&](int chunk, int s) {
        const int k0 = chunk * 32;
        const uint32_t sstage = stile + s * STAGEB;
        #pragma unroll
        for (int i = 0; i < 4; i++) {
            int idx = lwi + i * 128;
            int row = idx >> 2;
            int seg = idx & 3;
            uint32_t dst = sstage + (uint32_t)(row * TPITCHB + seg * 16);
            const void* src;
            if (ltile == 0) {
                src = X16 + (size_t)(m0 + row) * KK + k0 + seg * 8;
            } else if (ltile == 1) {
                src = (seg < 2)
                    ? (const void*)(X8h + (size_t)(m0 + row) * KK + k0 + seg * 16)
                    : (const void*)(X8l + (size_t)(m0 + row) * KK + k0 + (seg - 2) * 16);
            } else if (ltile == 2) {
                src = W16 + (size_t)(n0 + row) * KK + k0 + seg * 8;
            } else {
                src = (seg < 2)
                    ? (const void*)(W8l + (size_t)(n0 + row) * KK + k0 + seg * 16)
                    : (const void*)(W8h + (size_t)(n0 + row) * KK + k0 + (seg - 2) * 16);
            }
            cp_async16(dst, src);
        }
    };

    const uint32_t aoff = (uint32_t)((wm * 32 + (lane & 15)) * TPITCHB + (lane >> 4) * 16);
    const uint32_t boff = (uint32_t)((wn * 32 + ((lane >> 4) << 3) + (lane & 7)) * TPITCHB
                                     + ((lane >> 3) & 1) * 16);

    float acch[2][4][4];
    float accc[2][4][4];
    #pragma unroll
    for (int mt = 0; mt < 2; mt++)
        #pragma unroll
        for (int nt = 0; nt < 4; nt++)
            #pragma unroll
            for (int r = 0; r < 4; r++) { acch[mt][nt][r] = 0.f; accc[mt][nt][r] = 0.f; }

    load_stage(0, 0); CP_COMMIT();
    load_stage(1, 1); CP_COMMIT();
    load_stage(2, 2); CP_COMMIT();

    for (int t = 0; t < NCHUNK; t++) {
        const int s = t & 3;
        CP_WAIT2();
        __syncthreads();

        if (t + 3 < NCHUNK) load_stage(t + 3, (t + 3) & 3);
        CP_COMMIT();

        const uint32_t stXh = sb + s * STAGEB;
        const uint32_t stX8 = stXh + TILEB;
        const uint32_t stWh = stXh + 2 * TILEB;
        const uint32_t stW8 = stXh + 3 * TILEB;

        // fp16 hi*hi term (2 k16 steps)
        #pragma unroll
        for (int ks = 0; ks < 2; ks++) {
            uint32_t ah[2][4], bh[4][2];
            #pragma unroll
            for (int mt = 0; mt < 2; mt++)
                LDSM4(ah[mt][0], ah[mt][1], ah[mt][2], ah[mt][3],
                      stXh + aoff + mt * (16 * TPITCHB) + ks * 32);
            #pragma unroll
            for (int bt = 0; bt < 2; bt++) {
                uint32_t r0, r1, r2, r3;
                LDSM4(r0, r1, r2, r3, stWh + boff + bt * (16 * TPITCHB) + ks * 32);
                bh[bt * 2][0] = r0; bh[bt * 2][1] = r1;
                bh[bt * 2 + 1][0] = r2; bh[bt * 2 + 1][1] = r3;
            }
            #pragma unroll
            for (int mt = 0; mt < 2; mt++)
                #pragma unroll
                for (int nt = 0; nt < 4; nt++)
                    MMAF16(acch[mt][nt], ah[mt], bh[nt]);
        }

        // fp8 cross term (2 k32-fp8 steps == full [x8h|x8l]x[w8l|w8h] concat)
        #pragma unroll
        for (int ks = 0; ks < 2; ks++) {
            uint32_t a8[2][4], b8[4][2];
            #pragma unroll
            for (int mt = 0; mt < 2; mt++)
                LDSM4(a8[mt][0], a8[mt][1], a8[mt][2], a8[mt][3],
                      stX8 + aoff + mt * (16 * TPITCHB) + ks * 32);
            #pragma unroll
            for (int bt = 0; bt < 2; bt++) {
                uint32_t r0, r1, r2, r3;
                LDSM4(r0, r1, r2, r3, stW8 + boff + bt * (16 * TPITCHB) + ks * 32);
                b8[bt * 2][0] = r0; b8[bt * 2][1] = r1;
                b8[bt * 2 + 1][0] = r2; b8[bt * 2 + 1][1] = r3;
            }
            #pragma unroll
            for (int mt = 0; mt < 2; mt++)
                #pragma unroll
                for (int nt = 0; nt < 4; nt++)
                    MMAF8(accc[mt][nt], a8[mt], b8[nt]);
        }
    }

    // ---- epilogue: combine terms, store ----
    __nv_bfloat16* Yhi = (z == 0) ? Y0hi : (z == 1) ? Y1hi : Y2hi;
    __nv_bfloat16* Ylo = (z == 0) ? Y0lo : (z == 1) ? Y1lo : Y2lo;
    #pragma unroll
    for (int mt = 0; mt < 2; mt++) {
        const int mrow = m0 + wm * 32 + mt * 16 + (lane >> 2);
        #pragma unroll
        for (int nt = 0; nt < 4; nt++) {
            const int ncl = wn * 32 + nt * 8 + (lane & 3) * 2;
            float a0 = acch[mt][nt][0] + accc[mt][nt][0] * SC_INV;
            float a1 = acch[mt][nt][1] + accc[mt][nt][1] * SC_INV;
            float a2 = acch[mt][nt][2] + accc[mt][nt][2] * SC_INV;
            float a3 = acch[mt][nt][3] + accc[mt][nt][3] * SC_INV;
            if (qkv) {
                const int b = mrow >> 11;
                const int srow = mrow & 2047;
                const int h = n0 >> 7;
                size_t idx0 = (((size_t)(b * HH + h) * SS) + srow) * HD + ncl;
                size_t idx1 = idx0 + (size_t)8 * HD;
                __nv_bfloat16 h0 = __float2bfloat16(a0), h1 = __float2bfloat16(a1);
                __nv_bfloat16 h2 = __float2bfloat16(a2), h3 = __float2bfloat16(a3);
                *(uint32_t*)(Yhi + idx0) = packbf(a0, a1);
                *(uint32_t*)(Yhi + idx1) = packbf(a2, a3);
                *(uint32_t*)(Ylo + idx0) =
                    packbf(a0 - __bfloat162float(h0), a1 - __bfloat162float(h1));
                *(uint32_t*)(Ylo + idx1) =
                    packbf(a2 - __bfloat162float(h2), a3 - __bfloat162float(h3));
            } else {
                float* basep = Yf + (size_t)mrow * DD + n0 + ncl;
                *(float2*)basep = make_float2(a0, a1);
                *(float2*)(basep + (size_t)8 * DD) = make_float2(a2, a3);
            }
        }
    }
}

// ---------------------------------------------------------------------------
// HMMA flash attention, split-bf16 (3 terms), epilogue emits fp16+fp8 operands
// for the output projection.
// ---------------------------------------------------------------------------
#define APITCH   272
#define PPITCH   144
#define AQTILE   (64 * APITCH)
#define AKV_STAGE (4 * AQTILE)
#define AOFF_Q    0
#define AOFF_STAGE (2 * AQTILE)
#define AOFF_P    (AOFF_STAGE + 2 * AKV_STAGE)
#define AOFF_PLO  (AOFF_P + 64 * PPITCH)
#define AOFF_STAT (AOFF_PLO + 64 * PPITCH)
#define ATT_SMEM  (AOFF_STAT + 1024)
#define NKV       (SS / 64)

__global__ __launch_bounds__(256, 1) void attn_hmma(
    const __nv_bfloat16* __restrict__ Qhi_g, const __nv_bfloat16* __restrict__ Qlo_g,
    const __nv_bfloat16* __restrict__ Khi_g, const __nv_bfloat16* __restrict__ Klo_g,
    const __nv_bfloat16* __restrict__ Vhi_g, const __nv_bfloat16* __restrict__ Vlo_g,
    __half* __restrict__ A16, uint8_t* __restrict__ A8h, uint8_t* __restrict__ A8l)
{
    extern __shared__ char smem[];
    const uint32_t sb = smem_to_u32(smem);
    float* rowmax = (float*)(smem + AOFF_STAT);
    float* rowsum = rowmax + 128;

    const int tid  = threadIdx.x;
    const int wid  = tid >> 5;
    const int lane = tid & 31;
    const int wm   = wid >> 1;
    const int wn   = wid & 1;
    const int q0   = blockIdx.x * 64;
    const int bh   = blockIdx.y;
    const size_t bhoff = (size_t)bh * SS * HD;

    {
        const __nv_bfloat16* qh = Qhi_g + bhoff + (size_t)q0 * HD;
        const __nv_bfloat16* ql = Qlo_g + bhoff + (size_t)q0 * HD;
        for (int i = tid; i < 64 * 16; i += 256) {
            int r = i >> 4, c = i & 15;
            *(uint4*)(smem + AOFF_Q + r * APITCH + c * 16) =
                *(const uint4*)(qh + (size_t)r * HD + c * 8);
            *(uint4*)(smem + AOFF_Q + AQTILE + r * APITCH + c * 16) =
                *(const uint4*)(ql + (size_t)r * HD + c * 8);
        }
    }

    const __nv_bfloat16* kvbase[4] = {Khi_g + bhoff, Klo_g + bhoff,
                                      Vhi_g + bhoff, Vlo_g + bhoff};
    auto load_kv = [&](int chunk, int s) {
        const uint32_t sstage = sb + AOFF_STAGE + s * AKV_STAGE;
        #pragma unroll
        for (int t = 0; t < 16; t++) {
            int tile = t >> 2;
            int r = (16 * t + (tid >> 4)) & 63;
            int c = tid & 15;
            cp_async16(sstage + tile * AQTILE + r * APITCH + c * 16,
                       kvbase[tile] + (size_t)(chunk * 64 + r) * HD + c * 8);
        }
    };

    const uint32_t qBaseHi = sb + AOFF_Q + (wm * 16 + (lane & 15)) * APITCH + (lane >> 4) * 16;
    const uint32_t kFragOff = (uint32_t)((wn * 32 + ((lane >> 4) << 3) + (lane & 7)) * APITCH
                                         + ((lane >> 3) & 1) * 16);
    const uint32_t pBaseHi = sb + AOFF_P + (wm * 16 + (lane & 15)) * PPITCH + (lane >> 4) * 16;
    const int vRow = ((lane >> 3) & 1) * 8 + (lane & 7);
    const uint32_t vCol = (uint32_t)(wn * 128 + (lane >> 4) * 16);

    const int rl0 = wm * 16 + (lane >> 2);

    float of[8][4];
    #pragma unroll
    for (int i = 0; i < 8; i++)
        #pragma unroll
        for (int j = 0; j < 4; j++) of[i][j] = 0.f;
    float m0 = -1e30f, m1 = -1e30f, l0 = 0.f, l1 = 0.f;

    const float sm_scale = 0.08838834764831843f;

    load_kv(0, 0); CP_COMMIT();
    load_kv(1, 1); CP_COMMIT();

    for (int t = 0; t < NKV; t++) {
        const int s = t & 1;
        CP_WAIT1();
        __syncthreads();

        const uint32_t sK  = sb + AOFF_STAGE + s * AKV_STAGE;
        const uint32_t sKl = sK + AQTILE;
        const uint32_t sV  = sK + 2 * AQTILE;
        const uint32_t sVl = sK + 3 * AQTILE;

        float sf[4][4];
        #pragma unroll
        for (int nt = 0; nt < 4; nt++)
            #pragma unroll
            for (int j = 0; j < 4; j++) sf[nt][j] = 0.f;

        #pragma unroll
        for (int ks = 0; ks < 8; ks++) {
            uint32_t qh[4], ql[4], kh[4][2], kl[4][2];
            LDSM4(qh[0], qh[1], qh[2], qh[3], qBaseHi + ks * 32);
            LDSM4(ql[0], ql[1], ql[2], ql[3], qBaseHi + AQTILE + ks * 32);
            #pragma unroll
            for (int bt = 0; bt < 2; bt++) {
                uint32_t r0, r1, r2, r3;
                LDSM4(r0, r1, r2, r3, sK + kFragOff + bt * (16 * APITCH) + ks * 32);
                kh[bt * 2][0] = r0; kh[bt * 2][1] = r1;
                kh[bt * 2 + 1][0] = r2; kh[bt * 2 + 1][1] = r3;
                LDSM4(r0, r1, r2, r3, sKl + kFragOff + bt * (16 * APITCH) + ks * 32);
                kl[bt * 2][0] = r0; kl[bt * 2][1] = r1;
                kl[bt * 2 + 1][0] = r2; kl[bt * 2 + 1][1] = r3;
            }
            #pragma unroll
            for (int nt = 0; nt < 4; nt++) {
                MMA16816(sf[nt], qh, kh[nt]);
                MMA16816(sf[nt], qh, kl[nt]);
                MMA16816(sf[nt], ql, kh[nt]);
            }
        }

        #pragma unroll
        for (int nt = 0; nt < 4; nt++)
            #pragma unroll
            for (int j = 0; j < 4; j++) sf[nt][j] *= sm_scale;

        float mx0 = -1e30f, mx1 = -1e30f;
        #pragma unroll
        for (int nt = 0; nt < 4; nt++) {
            mx0 = fmaxf(mx0, fmaxf(sf[nt][0], sf[nt][1]));
            mx1 = fmaxf(mx1, fmaxf(sf[nt][2], sf[nt][3]));
        }
        mx0 = fmaxf(mx0, __shfl_xor_sync(0xffffffffu, mx0, 1));
        mx0 = fmaxf(mx0, __shfl_xor_sync(0xffffffffu, mx0, 2));
        mx1 = fmaxf(mx1, __shfl_xor_sync(0xffffffffu, mx1, 1));
        mx1 = fmaxf(mx1, __shfl_xor_sync(0xffffffffu, mx1, 2));
        if ((lane & 3) == 0) {
            rowmax[wn * 64 + rl0]     = mx0;
            rowmax[wn * 64 + rl0 + 8] = mx1;
        }
        __syncthreads();

        const float mn0 = fmaxf(m0, fmaxf(rowmax[rl0], rowmax[64 + rl0]));
        const float mn1 = fmaxf(m1, fmaxf(rowmax[rl0 + 8], rowmax[64 + rl0 + 8]));
        const float al0 = __expf(m0 - mn0);
        const float al1 = __expf(m1 - mn1);

        float sum0 = 0.f, sum1 = 0.f;
        #pragma unroll
        for (int nt = 0; nt < 4; nt++) {
            float p00 = __expf(sf[nt][0] - mn0);
            float p01 = __expf(sf[nt][1] - mn0);
            float p10 = __expf(sf[nt][2] - mn1);
            float p11 = __expf(sf[nt][3] - mn1);
            sum0 += p00 + p01;
            sum1 += p10 + p11;
            const uint32_t coff = (uint32_t)(wn * 64 + nt * 16 + (lane & 3) * 4);
            __nv_bfloat16 h00 = __float2bfloat16(p00), h01 = __float2bfloat16(p01);
            __nv_bfloat16 h10 = __float2bfloat16(p10), h11 = __float2bfloat16(p11);
            *(uint32_t*)(smem + AOFF_P + rl0 * PPITCH + coff) = packbf(p00, p01);
            *(uint32_t*)(smem + AOFF_P + (rl0 + 8) * PPITCH + coff) = packbf(p10, p11);
            *(uint32_t*)(smem + AOFF_PLO + rl0 * PPITCH + coff) =
                packbf(p00 - __bfloat162float(h00), p01 - __bfloat162float(h01));
            *(uint32_t*)(smem + AOFF_PLO + (rl0 + 8) * PPITCH + coff) =
                packbf(p10 - __bfloat162float(h10), p11 - __bfloat162float(h11));
        }
        sum0 += __shfl_xor_sync(0xffffffffu, sum0, 1);
        sum0 += __shfl_xor_sync(0xffffffffu, sum0, 2);
        sum1 += __shfl_xor_sync(0xffffffffu, sum1, 1);
        sum1 += __shfl_xor_sync(0xffffffffu, sum1, 2);
        if ((lane & 3) == 0) {
            rowsum[wn * 64 + rl0]     = sum0;
            rowsum[wn * 64 + rl0 + 8] = sum1;
        }
        __syncthreads();

        l0 = l0 * al0 + rowsum[rl0] + rowsum[64 + rl0];
        l1 = l1 * al1 + rowsum[rl0 + 8] + rowsum[64 + rl0 + 8];
        m0 = mn0; m1 = mn1;

        #pragma unroll
        for (int nt = 0; nt < 8; nt++) {
            of[nt][0] *= al0; of[nt][1] *= al0;
            of[nt][2] *= al1; of[nt][3] *= al1;
        }

        #pragma unroll
        for (int ks = 0; ks < 4; ks++) {
            uint32_t ph[4], pl[4];
            LDSM4(ph[0], ph[1], ph[2], ph[3], pBaseHi + ks * 32);
            LDSM4(pl[0], pl[1], pl[2], pl[3], pBaseHi + (64 * PPITCH) + ks * 32);
            const uint32_t vro = (uint32_t)((ks * 16 + vRow) * APITCH) + vCol;
            #pragma unroll
            for (int nt2 = 0; nt2 < 4; nt2++) {
                uint32_t r0, r1, r2, r3;
                uint32_t vh0[2], vh1[2], vl0[2], vl1[2];
                LDSM4T(r0, r1, r2, r3, sV + vro + nt2 * 32);
                vh0[0] = r0; vh0[1] = r1; vh1[0] = r2; vh1[1] = r3;
                LDSM4T(r0, r1, r2, r3, sVl + vro + nt2 * 32);
                vl0[0] = r0; vl0[1] = r1; vl1[0] = r2; vl1[1] = r3;
                MMA16816(of[nt2 * 2], ph, vh0);
                MMA16816(of[nt2 * 2], pl, vh0);
                MMA16816(of[nt2 * 2], ph, vl0);
                MMA16816(of[nt2 * 2 + 1], ph, vh1);
                MMA16816(of[nt2 * 2 + 1], pl, vh1);
                MMA16816(of[nt2 * 2 + 1], ph, vl1);
            }
        }

        __syncthreads();
        if (t + 2 < NKV) { load_kv(t + 2, s); CP_COMMIT(); }
    }

    // ---- epilogue: O/l -> fp16 hi + fp8 pair at [b, s, d] ----
    const int b = bh >> 4;
    const int h = bh & 15;
    const float inv0 = 1.0f / l0;
    const float inv1 = 1.0f / l1;
    const int s0 = q0 + rl0;
    #pragma unroll
    for (int nt = 0; nt < 8; nt++) {
        const int d = h * 128 + wn * 64 + nt * 8 + (lane & 3) * 2;
        size_t idx0 = ((size_t)(b * SS + s0)) * DD + d;
        size_t idx1 = idx0 + (size_t)8 * DD;
        float a0 = of[nt][0] * inv0, a1 = of[nt][1] * inv0;
        float a2 = of[nt][2] * inv1, a3 = of[nt][3] * inv1;
        __half p0 = __float2half(a0), p1 = __float2half(a1);
        __half p2 = __float2half(a2), p3 = __float2half(a3);
        float f0 = __half2float(p0), f1 = __half2float(p1);
        float f2 = __half2float(p2), f3 = __half2float(p3);
        *(uint32_t*)(A16 + idx0) = packh2(p0, p1);
        *(uint32_t*)(A16 + idx1) = packh2(p2, p3);
        *(uint16_t*)(A8h + idx0) =
            (uint16_t)f2e4m3(f0 * SC_HI) | ((uint16_t)f2e4m3(f1 * SC_HI) << 8);
        *(uint16_t*)(A8h + idx1) =
            (uint16_t)f2e4m3(f2 * SC_HI) | ((uint16_t)f2e4m3(f3 * SC_HI) << 8);
        *(uint16_t*)(A8l + idx0) =
            (uint16_t)f2e4m3((a0 - f0) * SC_LO) | ((uint16_t)f2e4m3((a1 - f1) * SC_LO) << 8);
        *(uint16_t*)(A8l + idx1) =
            (uint16_t)f2e4m3((a2 - f2) * SC_LO) | ((uint16_t)f2e4m3((a3 - f3) * SC_LO) << 8);
    }
}

// ---------------------------------------------------------------------------
extern "C" void kernel_launch(void* const* d_in, const int* in_sizes, int n_in,
                              void* d_out, int out_size)
{
    const float* x  = (const float*)d_in[0];
    const float* Wq = (const float*)d_in[1];
    const float* Wk = (const float*)d_in[2];
    const float* Wv = (const float*)d_in[3];
    const float* Wo = (const float*)d_in[4];

    __half *x16, *w16, *a16;
    uint8_t *x8h, *x8l, *w8h, *w8l, *a8h, *a8l;
    __nv_bfloat16 *qhi, *qlo, *khi, *klo, *vhi, *vlo;
    cudaGetSymbolAddress((void**)&x16, g_x16);
    cudaGetSymbolAddress((void**)&x8h, g_x8h);
    cudaGetSymbolAddress((void**)&x8l, g_x8l);
    cudaGetSymbolAddress((void**)&w16, g_w16);
    cudaGetSymbolAddress((void**)&w8h, g_w8h);
    cudaGetSymbolAddress((void**)&w8l, g_w8l);
    cudaGetSymbolAddress((void**)&a16, g_a16);
    cudaGetSymbolAddress((void**)&a8h, g_a8h);
    cudaGetSymbolAddress((void**)&a8l, g_a8l);
    cudaGetSymbolAddress((void**)&qhi, g_qhi);
    cudaGetSymbolAddress((void**)&qlo, g_qlo);
    cudaGetSymbolAddress((void**)&khi, g_khi);
    cudaGetSymbolAddress((void**)&klo, g_klo);
    cudaGetSymbolAddress((void**)&vhi, g_vhi);
    cudaGetSymbolAddress((void**)&vlo, g_vlo);

    cudaFuncSetAttribute(gemm_hmma, cudaFuncAttributeMaxDynamicSharedMemorySize,
                         GSMEM_TOTAL);
    cudaFuncSetAttribute(attn_hmma, cudaFuncAttributeMaxDynamicSharedMemorySize,
                         ATT_SMEM);

    const int xn4 = (int)((size_t)MTOT * DD / 4);
    const int wn4 = (int)((size_t)DD * DD / 4);

    split_all_kernel<<<dim3((xn4 + 255) / 256, 5), 256>>>(
        x, Wq, Wk, Wv, Wo, x16, x8h, x8l, w16, w8h, w8l, xn4, wn4);

    dim3 gqkv(DD / 128, MTOT / 128, 3);
    gemm_hmma<<<gqkv, 512, GSMEM_TOTAL>>>(x16, x8h, x8l, w16, w8h, w8l, nullptr,
                                          qhi, qlo, khi, klo, vhi, vlo, 1);

    attn_hmma<<<dim3(SS / 64, Bb * HH), 256, ATT_SMEM>>>(
        qhi, qlo, khi, klo, vhi, vlo, a16, a8h, a8l);

    dim3 go(DD / 128, MTOT / 128, 1);
    gemm_hmma<<<go, 512, GSMEM_TOTAL>>>(a16, a8h, a8l,
                                        w16 + (size_t)3 * DD * DD,
                                        w8h + (size_t)3 * DD * DD,
                                        w8l + (size_t)3 * DD * DD,
                                        (float*)d_out,
                                        nullptr, nullptr, nullptr, nullptr,
                                        nullptr, nullptr, 0);
}

// round 9
// speedup vs baseline: 1.1743x; 1.1743x over previous
#include <cuda_runtime.h>
#include <cuda_bf16.h>
#include <stdint.h>
#include <math.h>

// Problem constants
#define Bb   2
#define SS   2048
#define DD   2048
#define HH   16
#define HD   128
#define MTOT 4096   // Bb*SS
#define KK   2048

// ---------------------------------------------------------------------------
// Scratch (device globals: allocation-free rule)
// ---------------------------------------------------------------------------
__device__ __nv_bfloat16 g_xhi[(size_t)MTOT * DD];
__device__ __nv_bfloat16 g_xlo[(size_t)MTOT * DD];
__device__ __nv_bfloat16 g_whi[(size_t)4 * DD * DD];  // Wq,Wk,Wv,Wo
__device__ __nv_bfloat16 g_wlo[(size_t)4 * DD * DD];
__device__ __nv_bfloat16 g_qhi[(size_t)Bb * HH * SS * HD];  // [b,h,s,hd]
__device__ __nv_bfloat16 g_qlo[(size_t)Bb * HH * SS * HD];
__device__ __nv_bfloat16 g_khi[(size_t)Bb * HH * SS * HD];
__device__ __nv_bfloat16 g_klo[(size_t)Bb * HH * SS * HD];
__device__ __nv_bfloat16 g_vhi[(size_t)Bb * HH * SS * HD];
__device__ __nv_bfloat16 g_vlo[(size_t)Bb * HH * SS * HD];
__device__ __nv_bfloat16 g_ahi[(size_t)MTOT * DD];          // attn out [b,s,d]
__device__ __nv_bfloat16 g_alo[(size_t)MTOT * DD];

// ---------------------------------------------------------------------------
// PTX helpers (family-safe: sm_80-class instructions only)
// ---------------------------------------------------------------------------
__device__ __forceinline__ uint32_t smem_to_u32(const void* p) {
    uint32_t a;
    asm("{ .reg .u64 t; cvta.to.shared.u64 t, %1; cvt.u32.u64 %0, t; }"
        : "=r"(a) : "l"(p));
    return a;
}

__device__ __forceinline__ void cp_async16(uint32_t saddr, const void* gaddr) {
    asm volatile("cp.async.cg.shared.global [%0], [%1], 16;"
                 :: "r"(saddr), "l"(gaddr) : "memory");
}
#define CP_COMMIT() asm volatile("cp.async.commit_group;" ::: "memory")
#define CP_WAIT1()  asm volatile("cp.async.wait_group 1;" ::: "memory")
#define CP_WAIT2()  asm volatile("cp.async.wait_group 2;" ::: "memory")

#define LDSM4(r0, r1, r2, r3, addr) \
    asm volatile("ldmatrix.sync.aligned.m8n8.x4.shared.b16 {%0,%1,%2,%3}, [%4];" \
                 : "=r"(r0), "=r"(r1), "=r"(r2), "=r"(r3) : "r"(addr))

#define LDSM4T(r0, r1, r2, r3, addr) \
    asm volatile("ldmatrix.sync.aligned.m8n8.x4.trans.shared.b16 {%0,%1,%2,%3}, [%4];" \
                 : "=r"(r0), "=r"(r1), "=r"(r2), "=r"(r3) : "r"(addr))

#define MMA16816(d, a, b) \
    asm volatile("mma.sync.aligned.m16n8k16.row.col.f32.bf16.bf16.f32 " \
                 "{%0,%1,%2,%3}, {%4,%5,%6,%7}, {%8,%9}, {%0,%1,%2,%3};" \
                 : "+f"((d)[0]), "+f"((d)[1]), "+f"((d)[2]), "+f"((d)[3]) \
                 : "r"((a)[0]), "r"((a)[1]), "r"((a)[2]), "r"((a)[3]), \
                   "r"((b)[0]), "r"((b)[1]))

__device__ __forceinline__ uint32_t packbf(float x, float y) {
    __nv_bfloat162 t = __floats2bfloat162_rn(x, y);
    return *(uint32_t*)&t;
}

// ---------------------------------------------------------------------------
// Fused split: one launch handles x and all 4 weights.
// blockIdx.y: 0 -> x, 1..4 -> W[y-1].
// ---------------------------------------------------------------------------
__global__ __launch_bounds__(256) void split_all_kernel(
    const float* __restrict__ x,  const float* __restrict__ Wq,
    const float* __restrict__ Wk, const float* __restrict__ Wv,
    const float* __restrict__ Wo,
    __nv_bfloat16* __restrict__ xhi, __nv_bfloat16* __restrict__ xlo,
    __nv_bfloat16* __restrict__ whi, __nv_bfloat16* __restrict__ wlo,
    int xn4, int wn4)
{
    const int y = blockIdx.y;
    const float* in;
    __nv_bfloat16 *hi, *lo;
    int n4;
    if (y == 0) { in = x; hi = xhi; lo = xlo; n4 = xn4; }
    else {
        const float* ws[4] = {Wq, Wk, Wv, Wo};
        in = ws[y - 1];
        const size_t off = (size_t)(y - 1) * DD * DD;
        hi = whi + off; lo = wlo + off; n4 = wn4;
    }
    int i = blockIdx.x * blockDim.x + threadIdx.x;
    if (i >= n4) return;
    float4 v = ((const float4*)in)[i];
    __nv_bfloat16 h0 = __float2bfloat16(v.x);
    __nv_bfloat16 h1 = __float2bfloat16(v.y);
    __nv_bfloat16 h2 = __float2bfloat16(v.z);
    __nv_bfloat16 h3 = __float2bfloat16(v.w);
    ((__nv_bfloat162*)hi)[2 * i + 0] = __halves2bfloat162(h0, h1);
    ((__nv_bfloat162*)hi)[2 * i + 1] = __halves2bfloat162(h2, h3);
    ((__nv_bfloat162*)lo)[2 * i + 0] = __halves2bfloat162(
        __float2bfloat16(v.x - __bfloat162float(h0)),
        __float2bfloat16(v.y - __bfloat162float(h1)));
    ((__nv_bfloat162*)lo)[2 * i + 1] = __halves2bfloat162(
        __float2bfloat16(v.z - __bfloat162float(h2)),
        __float2bfloat16(v.w - __bfloat162float(h3)));
}

// ---------------------------------------------------------------------------
// HMMA GEMM (Round-6 best): split-bf16 3-term, 512 threads / 16 warps,
// warp tile 32x32, CTA 128x128, BK=32, 4-stage cp.async, one barrier/chunk.
// ---------------------------------------------------------------------------
#define TPITCHB  80
#define TILEB    10240         // 128 * 80
#define STAGEB   40960
#define NSTAGE   4
#define GSMEM_TOTAL (NSTAGE * STAGEB)
#define NCHUNK   (KK / 32)

__global__ __launch_bounds__(512, 1) void gemm_hmma(
    const __nv_bfloat16* __restrict__ Xhi, const __nv_bfloat16* __restrict__ Xlo,
    const __nv_bfloat16* __restrict__ WhiBase, const __nv_bfloat16* __restrict__ WloBase,
    float* __restrict__ Yf,
    __nv_bfloat16* __restrict__ Y0hi, __nv_bfloat16* __restrict__ Y0lo,
    __nv_bfloat16* __restrict__ Y1hi, __nv_bfloat16* __restrict__ Y1lo,
    __nv_bfloat16* __restrict__ Y2hi, __nv_bfloat16* __restrict__ Y2lo,
    int qkv)
{
    extern __shared__ char smem[];
    const uint32_t sb = smem_to_u32(smem);

    const int tid  = threadIdx.x;
    const int wid  = tid >> 5;
    const int lane = tid & 31;
    const int wm   = wid >> 2;
    const int wn   = wid & 3;
    const int m0   = blockIdx.y * 128;
    const int n0   = blockIdx.x * 128;
    const int z    = blockIdx.z;

    const __nv_bfloat16* Whi = WhiBase + (size_t)z * DD * DD;
    const __nv_bfloat16* Wlo = WloBase + (size_t)z * DD * DD;

    const int ltile = tid >> 7;
    const int lwi   = tid & 127;
    const __nv_bfloat16* gbase =
        (ltile == 0) ? Xhi : (ltile == 1) ? Xlo : (ltile == 2) ? Whi : Wlo;
    const int rowoff = (ltile < 2) ? m0 : n0;
    const uint32_t stile = sb + ltile * TILEB;

    auto load_stage = [&](int chunk, int s) {
        const int k0 = chunk * 32;
        const uint32_t sstage = stile + s * STAGEB;
        #pragma unroll
        for (int i = 0; i < 4; i++) {
            int idx = lwi + i * 128;
            int row = idx >> 2;
            int c   = idx & 3;
            cp_async16(sstage + (uint32_t)(row * TPITCHB + c * 16),
                       gbase + (size_t)(rowoff + row) * KK + k0 + c * 8);
        }
    };

    const uint32_t aoff = (uint32_t)((wm * 32 + (lane & 15)) * TPITCHB + (lane >> 4) * 16);
    const uint32_t boff = (uint32_t)((wn * 32 + ((lane >> 4) << 3) + (lane & 7)) * TPITCHB
                                     + ((lane >> 3) & 1) * 16);

    float acc[2][4][4];
    #pragma unroll
    for (int mt = 0; mt < 2; mt++)
        #pragma unroll
        for (int nt = 0; nt < 4; nt++)
            #pragma unroll
            for (int r = 0; r < 4; r++) acc[mt][nt][r] = 0.f;

    load_stage(0, 0); CP_COMMIT();
    load_stage(1, 1); CP_COMMIT();
    load_stage(2, 2); CP_COMMIT();

    for (int t = 0; t < NCHUNK; t++) {
        const int s = t & 3;
        CP_WAIT2();
        __syncthreads();

        if (t + 3 < NCHUNK) load_stage(t + 3, (t + 3) & 3);
        CP_COMMIT();

        const uint32_t stA  = sb + s * STAGEB;
        const uint32_t stAl = stA + TILEB;
        const uint32_t stB  = stA + 2 * TILEB;
        const uint32_t stBl = stA + 3 * TILEB;

        #pragma unroll
        for (int ks = 0; ks < 2; ks++) {
            uint32_t ah[2][4], al[2][4], bh[4][2], bl[4][2];
            #pragma unroll
            for (int mt = 0; mt < 2; mt++) {
                LDSM4(ah[mt][0], ah[mt][1], ah[mt][2], ah[mt][3],
                      stA  + aoff + mt * (16 * TPITCHB) + ks * 32);
                LDSM4(al[mt][0], al[mt][1], al[mt][2], al[mt][3],
                      stAl + aoff + mt * (16 * TPITCHB) + ks * 32);
            }
            #pragma unroll
            for (int bt = 0; bt < 2; bt++) {
                uint32_t r0, r1, r2, r3;
                LDSM4(r0, r1, r2, r3, stB + boff + bt * (16 * TPITCHB) + ks * 32);
                bh[bt * 2][0] = r0; bh[bt * 2][1] = r1;
                bh[bt * 2 + 1][0] = r2; bh[bt * 2 + 1][1] = r3;
                LDSM4(r0, r1, r2, r3, stBl + boff + bt * (16 * TPITCHB) + ks * 32);
                bl[bt * 2][0] = r0; bl[bt * 2][1] = r1;
                bl[bt * 2 + 1][0] = r2; bl[bt * 2 + 1][1] = r3;
            }
            #pragma unroll
            for (int mt = 0; mt < 2; mt++)
                #pragma unroll
                for (int nt = 0; nt < 4; nt++) {
                    MMA16816(acc[mt][nt], ah[mt], bh[nt]);
                    MMA16816(acc[mt][nt], ah[mt], bl[nt]);
                    MMA16816(acc[mt][nt], al[mt], bh[nt]);
                }
        }
    }

    // ---- epilogue ----
    __nv_bfloat16* Yhi = (z == 0) ? Y0hi : (z == 1) ? Y1hi : Y2hi;
    __nv_bfloat16* Ylo = (z == 0) ? Y0lo : (z == 1) ? Y1lo : Y2lo;
    #pragma unroll
    for (int mt = 0; mt < 2; mt++) {
        const int mrow = m0 + wm * 32 + mt * 16 + (lane >> 2);
        #pragma unroll
        for (int nt = 0; nt < 4; nt++) {
            const int ncl = wn * 32 + nt * 8 + (lane & 3) * 2;
            if (qkv) {
                const int b = mrow >> 11;
                const int srow = mrow & 2047;
                const int h = n0 >> 7;
                size_t idx0 = (((size_t)(b * HH + h) * SS) + srow) * HD + ncl;
                size_t idx1 = idx0 + (size_t)8 * HD;
                float a0 = acc[mt][nt][0], a1 = acc[mt][nt][1];
                float a2 = acc[mt][nt][2], a3 = acc[mt][nt][3];
                __nv_bfloat16 h0 = __float2bfloat16(a0), h1 = __float2bfloat16(a1);
                __nv_bfloat16 h2 = __float2bfloat16(a2), h3 = __float2bfloat16(a3);
                *(uint32_t*)(Yhi + idx0) = packbf(a0, a1);
                *(uint32_t*)(Yhi + idx1) = packbf(a2, a3);
                *(uint32_t*)(Ylo + idx0) =
                    packbf(a0 - __bfloat162float(h0), a1 - __bfloat162float(h1));
                *(uint32_t*)(Ylo + idx1) =
                    packbf(a2 - __bfloat162float(h2), a3 - __bfloat162float(h3));
            } else {
                float* basep = Yf + (size_t)mrow * DD + n0 + ncl;
                *(float2*)basep = make_float2(acc[mt][nt][0], acc[mt][nt][1]);
                *(float2*)(basep + (size_t)8 * DD) = make_float2(acc[mt][nt][2], acc[mt][nt][3]);
            }
        }
    }
}

// ---------------------------------------------------------------------------
// Flash attention v2-style: BQ=128, BKV=64, 8 warps, each warp owns 16 full
// q-rows across the whole kv width. Softmax is warp-local (quad shuffles);
// P stays in registers (S accum fragments repacked as PV A-fragments).
// 2 barriers per chunk (KV stage protection only). Split-bf16 3-term math.
// ---------------------------------------------------------------------------
#define APITCH    272
#define AQ_TILE   (128 * APITCH)     // 34816 (one of hi/lo)
#define AKV_TILE  (64 * APITCH)      // 17408
#define AOFF_Q    0
#define AOFF_STAGE (2 * AQ_TILE)     // 69632
#define AKV_STAGE (4 * AKV_TILE)     // 69632
#define ATT_SMEM  (AOFF_STAGE + 2 * AKV_STAGE)   // 208896
#define NKV       (SS / 64)

__global__ __launch_bounds__(256, 1) void attn_hmma(
    const __nv_bfloat16* __restrict__ Qhi_g, const __nv_bfloat16* __restrict__ Qlo_g,
    const __nv_bfloat16* __restrict__ Khi_g, const __nv_bfloat16* __restrict__ Klo_g,
    const __nv_bfloat16* __restrict__ Vhi_g, const __nv_bfloat16* __restrict__ Vlo_g,
    __nv_bfloat16* __restrict__ Ahi, __nv_bfloat16* __restrict__ Alo)
{
    extern __shared__ char smem[];
    const uint32_t sb = smem_to_u32(smem);

    const int tid  = threadIdx.x;
    const int wid  = tid >> 5;     // 0..7: q-row band of 16
    const int lane = tid & 31;
    const int q0   = blockIdx.x * 128;
    const int bh   = blockIdx.y;
    const size_t bhoff = (size_t)bh * SS * HD;

    // ---- load Q (hi,lo): 128 rows x 128 cols ----
    {
        const __nv_bfloat16* qh = Qhi_g + bhoff + (size_t)q0 * HD;
        const __nv_bfloat16* ql = Qlo_g + bhoff + (size_t)q0 * HD;
        for (int i = tid; i < 128 * 16; i += 256) {
            int r = i >> 4, c = i & 15;
            *(uint4*)(smem + AOFF_Q + r * APITCH + c * 16) =
                *(const uint4*)(qh + (size_t)r * HD + c * 8);
            *(uint4*)(smem + AOFF_Q + AQ_TILE + r * APITCH + c * 16) =
                *(const uint4*)(ql + (size_t)r * HD + c * 8);
        }
    }

    const __nv_bfloat16* kvbase[4] = {Khi_g + bhoff, Klo_g + bhoff,
                                      Vhi_g + bhoff, Vlo_g + bhoff};
    auto load_kv = [&](int chunk, int s) {
        const uint32_t sstage = sb + AOFF_STAGE + s * AKV_STAGE;
        #pragma unroll
        for (int t = 0; t < 16; t++) {
            int tile = t >> 2;
            int r = (16 * t + (tid >> 4)) & 63;
            int c = tid & 15;
            cp_async16(sstage + tile * AKV_TILE + r * APITCH + c * 16,
                       kvbase[tile] + (size_t)(chunk * 64 + r) * HD + c * 8);
        }
    };

    // A-fragment base for Q (m16 x k16), this warp's row band
    const uint32_t qBase = sb + AOFF_Q
        + (wid * 16 + (lane & 15)) * APITCH + (lane >> 4) * 16;
    // B-fragment offset for K (n16 x k16 per LDSM4)
    const uint32_t kFragOff = (uint32_t)((((lane >> 4) << 3) + (lane & 7)) * APITCH
                                         + ((lane >> 3) & 1) * 16);
    // V trans-fragment addressing
    const int vRow = ((lane >> 3) & 1) * 8 + (lane & 7);
    const uint32_t vColBase = (uint32_t)((lane >> 4) * 16);

    float of[16][4];
    #pragma unroll
    for (int i = 0; i < 16; i++)
        #pragma unroll
        for (int j = 0; j < 4; j++) of[i][j] = 0.f;
    float m0 = -1e30f, m1 = -1e30f, l0 = 0.f, l1 = 0.f;

    const float sm_scale = 0.08838834764831843f;  // 1/sqrt(128)

    load_kv(0, 0); CP_COMMIT();
    load_kv(1, 1); CP_COMMIT();

    for (int t = 0; t < NKV; t++) {
        const int s = t & 1;
        CP_WAIT1();
        __syncthreads();   // stage t resident + Q loaded (first iter)

        const uint32_t sK  = sb + AOFF_STAGE + s * AKV_STAGE;
        const uint32_t sKl = sK + AKV_TILE;
        const uint32_t sV  = sK + 2 * AKV_TILE;
        const uint32_t sVl = sK + 3 * AKV_TILE;

        // ---- S = Q K^T over full kv width (8 n8 tiles) ----
        float sf[8][4];
        #pragma unroll
        for (int nt = 0; nt < 8; nt++)
            #pragma unroll
            for (int j = 0; j < 4; j++) sf[nt][j] = 0.f;

        #pragma unroll
        for (int ks = 0; ks < 8; ks++) {
            uint32_t qh[4], ql[4], kh[8][2], kl[8][2];
            LDSM4(qh[0], qh[1], qh[2], qh[3], qBase + ks * 32);
            LDSM4(ql[0], ql[1], ql[2], ql[3], qBase + AQ_TILE + ks * 32);
            #pragma unroll
            for (int nk = 0; nk < 4; nk++) {
                uint32_t r0, r1, r2, r3;
                LDSM4(r0, r1, r2, r3, sK + nk * (16 * APITCH) + kFragOff + ks * 32);
                kh[nk * 2][0] = r0; kh[nk * 2][1] = r1;
                kh[nk * 2 + 1][0] = r2; kh[nk * 2 + 1][1] = r3;
                LDSM4(r0, r1, r2, r3, sKl + nk * (16 * APITCH) + kFragOff + ks * 32);
                kl[nk * 2][0] = r0; kl[nk * 2][1] = r1;
                kl[nk * 2 + 1][0] = r2; kl[nk * 2 + 1][1] = r3;
            }
            #pragma unroll
            for (int nt = 0; nt < 8; nt++) {
                MMA16816(sf[nt], qh, kh[nt]);
                MMA16816(sf[nt], qh, kl[nt]);
                MMA16816(sf[nt], ql, kh[nt]);
            }
        }

        // ---- warp-local online softmax (rows r0 = lane>>2, r0+8) ----
        #pragma unroll
        for (int nt = 0; nt < 8; nt++)
            #pragma unroll
            for (int j = 0; j < 4; j++) sf[nt][j] *= sm_scale;

        float mx0 = -1e30f, mx1 = -1e30f;
        #pragma unroll
        for (int nt = 0; nt < 8; nt++) {
            mx0 = fmaxf(mx0, fmaxf(sf[nt][0], sf[nt][1]));
            mx1 = fmaxf(mx1, fmaxf(sf[nt][2], sf[nt][3]));
        }
        mx0 = fmaxf(mx0, __shfl_xor_sync(0xffffffffu, mx0, 1));
        mx0 = fmaxf(mx0, __shfl_xor_sync(0xffffffffu, mx0, 2));
        mx1 = fmaxf(mx1, __shfl_xor_sync(0xffffffffu, mx1, 1));
        mx1 = fmaxf(mx1, __shfl_xor_sync(0xffffffffu, mx1, 2));

        const float mn0 = fmaxf(m0, mx0);
        const float mn1 = fmaxf(m1, mx1);
        const float al0 = __expf(m0 - mn0);
        const float al1 = __expf(m1 - mn1);

        float sum0 = 0.f, sum1 = 0.f;
        #pragma unroll
        for (int nt = 0; nt < 8; nt++) {
            sf[nt][0] = __expf(sf[nt][0] - mn0);
            sf[nt][1] = __expf(sf[nt][1] - mn0);
            sf[nt][2] = __expf(sf[nt][2] - mn1);
            sf[nt][3] = __expf(sf[nt][3] - mn1);
            sum0 += sf[nt][0] + sf[nt][1];
            sum1 += sf[nt][2] + sf[nt][3];
        }
        sum0 += __shfl_xor_sync(0xffffffffu, sum0, 1);
        sum0 += __shfl_xor_sync(0xffffffffu, sum0, 2);
        sum1 += __shfl_xor_sync(0xffffffffu, sum1, 1);
        sum1 += __shfl_xor_sync(0xffffffffu, sum1, 2);

        l0 = l0 * al0 + sum0;
        l1 = l1 * al1 + sum1;
        m0 = mn0; m1 = mn1;

        #pragma unroll
        for (int nt = 0; nt < 16; nt++) {
            of[nt][0] *= al0; of[nt][1] *= al0;
            of[nt][2] *= al1; of[nt][3] *= al1;
        }

        // ---- O += P V  (P from registers: S frags -> A frags) ----
        #pragma unroll
        for (int ks = 0; ks < 4; ks++) {
            const int t0 = 2 * ks, t1 = 2 * ks + 1;
            uint32_t ph[4], pl[4];
            ph[0] = packbf(sf[t0][0], sf[t0][1]);
            ph[1] = packbf(sf[t0][2], sf[t0][3]);
            ph[2] = packbf(sf[t1][0], sf[t1][1]);
            ph[3] = packbf(sf[t1][2], sf[t1][3]);
            {
                float d00 = sf[t0][0] - __bfloat162float(__float2bfloat16(sf[t0][0]));
                float d01 = sf[t0][1] - __bfloat162float(__float2bfloat16(sf[t0][1]));
                float d02 = sf[t0][2] - __bfloat162float(__float2bfloat16(sf[t0][2]));
                float d03 = sf[t0][3] - __bfloat162float(__float2bfloat16(sf[t0][3]));
                float d10 = sf[t1][0] - __bfloat162float(__float2bfloat16(sf[t1][0]));
                float d11 = sf[t1][1] - __bfloat162float(__float2bfloat16(sf[t1][1]));
                float d12 = sf[t1][2] - __bfloat162float(__float2bfloat16(sf[t1][2]));
                float d13 = sf[t1][3] - __bfloat162float(__float2bfloat16(sf[t1][3]));
                pl[0] = packbf(d00, d01);
                pl[1] = packbf(d02, d03);
                pl[2] = packbf(d10, d11);
                pl[3] = packbf(d12, d13);
            }
            const uint32_t vro = (uint32_t)((ks * 16 + vRow) * APITCH) + vColBase;
            #pragma unroll
            for (int nt4 = 0; nt4 < 8; nt4++) {
                uint32_t r0, r1, r2, r3;
                uint32_t vh0[2], vh1[2], vl0[2], vl1[2];
                LDSM4T(r0, r1, r2, r3, sV + vro + nt4 * 32);
                vh0[0] = r0; vh0[1] = r1; vh1[0] = r2; vh1[1] = r3;
                LDSM4T(r0, r1, r2, r3, sVl + vro + nt4 * 32);
                vl0[0] = r0; vl0[1] = r1; vl1[0] = r2; vl1[1] = r3;
                MMA16816(of[nt4 * 2], ph, vh0);
                MMA16816(of[nt4 * 2], pl, vh0);
                MMA16816(of[nt4 * 2], ph, vl0);
                MMA16816(of[nt4 * 2 + 1], ph, vh1);
                MMA16816(of[nt4 * 2 + 1], pl, vh1);
                MMA16816(of[nt4 * 2 + 1], ph, vl1);
            }
        }

        __syncthreads();   // all reads of stage s done before overwrite
        if (t + 2 < NKV) { load_kv(t + 2, s); CP_COMMIT(); }
    }

    // ---- epilogue: O/l -> bf16 hi/lo at [b, s, d] ----
    const int b = bh >> 4;
    const int h = bh & 15;
    const float inv0 = 1.0f / l0;
    const float inv1 = 1.0f / l1;
    const int s0 = q0 + wid * 16 + (lane >> 2);
    #pragma unroll
    for (int nt = 0; nt < 16; nt++) {
        const int d = h * 128 + nt * 8 + (lane & 3) * 2;
        size_t idx0 = ((size_t)(b * SS + s0)) * DD + d;
        size_t idx1 = idx0 + (size_t)8 * DD;
        float a0 = of[nt][0] * inv0, a1 = of[nt][1] * inv0;
        float a2 = of[nt][2] * inv1, a3 = of[nt][3] * inv1;
        __nv_bfloat16 h0 = __float2bfloat16(a0), h1 = __float2bfloat16(a1);
        __nv_bfloat16 h2 = __float2bfloat16(a2), h3 = __float2bfloat16(a3);
        *(uint32_t*)(Ahi + idx0) = packbf(a0, a1);
        *(uint32_t*)(Ahi + idx1) = packbf(a2, a3);
        *(uint32_t*)(Alo + idx0) = packbf(a0 - __bfloat162float(h0), a1 - __bfloat162float(h1));
        *(uint32_t*)(Alo + idx1) = packbf(a2 - __bfloat162float(h2), a3 - __bfloat162float(h3));
    }
}

// ---------------------------------------------------------------------------
extern "C" void kernel_launch(void* const* d_in, const int* in_sizes, int n_in,
                              void* d_out, int out_size)
{
    const float* x  = (const float*)d_in[0];
    const float* Wq = (const float*)d_in[1];
    const float* Wk = (const float*)d_in[2];
    const float* Wv = (const float*)d_in[3];
    const float* Wo = (const float*)d_in[4];

    __nv_bfloat16 *xhi, *xlo, *whi, *wlo;
    __nv_bfloat16 *qhi, *qlo, *khi, *klo, *vhi, *vlo, *ahi, *alo;
    cudaGetSymbolAddress((void**)&xhi, g_xhi);
    cudaGetSymbolAddress((void**)&xlo, g_xlo);
    cudaGetSymbolAddress((void**)&whi, g_whi);
    cudaGetSymbolAddress((void**)&wlo, g_wlo);
    cudaGetSymbolAddress((void**)&qhi, g_qhi);
    cudaGetSymbolAddress((void**)&qlo, g_qlo);
    cudaGetSymbolAddress((void**)&khi, g_khi);
    cudaGetSymbolAddress((void**)&klo, g_klo);
    cudaGetSymbolAddress((void**)&vhi, g_vhi);
    cudaGetSymbolAddress((void**)&vlo, g_vlo);
    cudaGetSymbolAddress((void**)&ahi, g_ahi);
    cudaGetSymbolAddress((void**)&alo, g_alo);

    cudaFuncSetAttribute(gemm_hmma, cudaFuncAttributeMaxDynamicSharedMemorySize,
                         GSMEM_TOTAL);
    cudaFuncSetAttribute(attn_hmma, cudaFuncAttributeMaxDynamicSharedMemorySize,
                         ATT_SMEM);

    const int xn4 = (int)((size_t)MTOT * DD / 4);
    const int wn4 = (int)((size_t)DD * DD / 4);

    split_all_kernel<<<dim3((xn4 + 255) / 256, 5), 256>>>(
        x, Wq, Wk, Wv, Wo, xhi, xlo, whi, wlo, xn4, wn4);

    dim3 gqkv(DD / 128, MTOT / 128, 3);
    gemm_hmma<<<gqkv, 512, GSMEM_TOTAL>>>(xhi, xlo, whi, wlo, nullptr,
                                          qhi, qlo, khi, klo, vhi, vlo, 1);

    attn_hmma<<<dim3(SS / 128, Bb * HH), 256, ATT_SMEM>>>(
        qhi, qlo, khi, klo, vhi, vlo, ahi, alo);

    dim3 go(DD / 128, MTOT / 128, 1);
    gemm_hmma<<<go, 512, GSMEM_TOTAL>>>(ahi, alo,
                                        whi + (size_t)3 * DD * DD,
                                        wlo + (size_t)3 * DD * DD,
                                        (float*)d_out,
                                        nullptr, nullptr, nullptr, nullptr,
                                        nullptr, nullptr, 0);
}

// round 10
// speedup vs baseline: 1.9194x; 1.6344x over previous
#include <cuda_runtime.h>
#include <cuda_bf16.h>
#include <cuda_fp16.h>
#include <stdint.h>
#include <math.h>

// Problem constants
#define Bb   2
#define SS   2048
#define DD   2048
#define HH   16
#define HD   128
#define MTOT 4096   // Bb*SS
#define KK   2048

// ---------------------------------------------------------------------------
// Scratch (device globals: allocation-free rule)
// ---------------------------------------------------------------------------
__device__ __half g_x16[(size_t)MTOT * DD];
__device__ __half g_w16[(size_t)4 * DD * DD];   // Wq,Wk,Wv,Wo (fp16)
__device__ __half g_a16[(size_t)MTOT * DD];     // attn out [b,s,d] (fp16)
__device__ __nv_bfloat16 g_qhi[(size_t)Bb * HH * SS * HD];  // [b,h,s,hd]
__device__ __nv_bfloat16 g_qlo[(size_t)Bb * HH * SS * HD];
__device__ __nv_bfloat16 g_khi[(size_t)Bb * HH * SS * HD];
__device__ __nv_bfloat16 g_klo[(size_t)Bb * HH * SS * HD];
__device__ __nv_bfloat16 g_vhi[(size_t)Bb * HH * SS * HD];
__device__ __nv_bfloat16 g_vlo[(size_t)Bb * HH * SS * HD];

// ---------------------------------------------------------------------------
// PTX helpers (family-safe: sm_80-class instructions only)
// ---------------------------------------------------------------------------
__device__ __forceinline__ uint32_t smem_to_u32(const void* p) {
    uint32_t a;
    asm("{ .reg .u64 t; cvta.to.shared.u64 t, %1; cvt.u32.u64 %0, t; }"
        : "=r"(a) : "l"(p));
    return a;
}

__device__ __forceinline__ void cp_async16(uint32_t saddr, const void* gaddr) {
    asm volatile("cp.async.cg.shared.global [%0], [%1], 16;"
                 :: "r"(saddr), "l"(gaddr) : "memory");
}
#define CP_COMMIT() asm volatile("cp.async.commit_group;" ::: "memory")
#define CP_WAIT1()  asm volatile("cp.async.wait_group 1;" ::: "memory")
#define CP_WAIT2()  asm volatile("cp.async.wait_group 2;" ::: "memory")

#define LDSM4(r0, r1, r2, r3, addr) \
    asm volatile("ldmatrix.sync.aligned.m8n8.x4.shared.b16 {%0,%1,%2,%3}, [%4];" \
                 : "=r"(r0), "=r"(r1), "=r"(r2), "=r"(r3) : "r"(addr))

#define LDSM4T(r0, r1, r2, r3, addr) \
    asm volatile("ldmatrix.sync.aligned.m8n8.x4.trans.shared.b16 {%0,%1,%2,%3}, [%4];" \
                 : "=r"(r0), "=r"(r1), "=r"(r2), "=r"(r3) : "r"(addr))

#define MMA16816(d, a, b) \
    asm volatile("mma.sync.aligned.m16n8k16.row.col.f32.bf16.bf16.f32 " \
                 "{%0,%1,%2,%3}, {%4,%5,%6,%7}, {%8,%9}, {%0,%1,%2,%3};" \
                 : "+f"((d)[0]), "+f"((d)[1]), "+f"((d)[2]), "+f"((d)[3]) \
                 : "r"((a)[0]), "r"((a)[1]), "r"((a)[2]), "r"((a)[3]), \
                   "r"((b)[0]), "r"((b)[1]))

#define MMAF16(d, a, b) \
    asm volatile("mma.sync.aligned.m16n8k16.row.col.f32.f16.f16.f32 " \
                 "{%0,%1,%2,%3}, {%4,%5,%6,%7}, {%8,%9}, {%0,%1,%2,%3};" \
                 : "+f"((d)[0]), "+f"((d)[1]), "+f"((d)[2]), "+f"((d)[3]) \
                 : "r"((a)[0]), "r"((a)[1]), "r"((a)[2]), "r"((a)[3]), \
                   "r"((b)[0]), "r"((b)[1]))

__device__ __forceinline__ uint32_t packbf(float x, float y) {
    __nv_bfloat162 t = __floats2bfloat162_rn(x, y);
    return *(uint32_t*)&t;
}
__device__ __forceinline__ uint32_t packh2(__half a, __half b) {
    __half2 t = __halves2half2(a, b);
    return *(uint32_t*)&t;
}

// ---------------------------------------------------------------------------
// Fused convert: x and all 4 weights -> fp16.  blockIdx.y: 0 -> x, 1..4 -> W.
// ---------------------------------------------------------------------------
__global__ __launch_bounds__(256) void split_all_kernel(
    const float* __restrict__ x,  const float* __restrict__ Wq,
    const float* __restrict__ Wk, const float* __restrict__ Wv,
    const float* __restrict__ Wo,
    __half* __restrict__ x16, __half* __restrict__ w16,
    int xn4, int wn4)
{
    const int y = blockIdx.y;
    const float* in;
    __half* h16;
    int n4;
    if (y == 0) { in = x; h16 = x16; n4 = xn4; }
    else {
        const float* ws[4] = {Wq, Wk, Wv, Wo};
        in = ws[y - 1];
        h16 = w16 + (size_t)(y - 1) * DD * DD;
        n4 = wn4;
    }
    int i = blockIdx.x * blockDim.x + threadIdx.x;
    if (i >= n4) return;
    float4 v = ((const float4*)in)[i];
    ((uint32_t*)h16)[2 * i + 0] = packh2(__float2half(v.x), __float2half(v.y));
    ((uint32_t*)h16)[2 * i + 1] = packh2(__float2half(v.z), __float2half(v.w));
}

// ---------------------------------------------------------------------------
// fp16 single-term GEMM:  Y[m,n] = sum_k X16[m,k] * W16[n,k]
// 512 threads / 16 warps, warp tile 32x32, CTA 128x128, BK=32,
// 4-stage cp.async, one barrier per chunk.
// qkv==1: gridDim.z selects weight slice; outputs split-bf16 Q/K/V [b,h,s,hd].
// qkv==0: fp32 output Yf.
// ---------------------------------------------------------------------------
#define TPITCHB  80
#define TILEB    10240         // 128 * 80
#define STAGEB   20480         // 2 tiles (X, W)
#define NSTAGE   4
#define GSMEM_TOTAL (NSTAGE * STAGEB)   // 81920
#define NCHUNK   (KK / 32)

__global__ __launch_bounds__(512, 1) void gemm_f16(
    const __half* __restrict__ X16, const __half* __restrict__ W16Base,
    float* __restrict__ Yf,
    __nv_bfloat16* __restrict__ Y0hi, __nv_bfloat16* __restrict__ Y0lo,
    __nv_bfloat16* __restrict__ Y1hi, __nv_bfloat16* __restrict__ Y1lo,
    __nv_bfloat16* __restrict__ Y2hi, __nv_bfloat16* __restrict__ Y2lo,
    int qkv)
{
    extern __shared__ char smem[];
    const uint32_t sb = smem_to_u32(smem);

    const int tid  = threadIdx.x;
    const int wid  = tid >> 5;
    const int lane = tid & 31;
    const int wm   = wid >> 2;    // 0..3
    const int wn   = wid & 3;     // 0..3
    const int m0   = blockIdx.y * 128;
    const int n0   = blockIdx.x * 128;
    const int z    = blockIdx.z;

    const __half* W16 = W16Base + (size_t)z * DD * DD;

    // loader: 2 groups of 256 threads (tile 0: X, tile 1: W)
    const int ltile = tid >> 8;
    const int lwi   = tid & 255;
    const __half* gbase = (ltile == 0) ? X16 : W16;
    const int rowoff = (ltile == 0) ? m0 : n0;
    const uint32_t stile = sb + ltile * TILEB;

    auto load_stage = [&](int chunk, int s) {
        const int k0 = chunk * 32;
        const uint32_t sstage = stile + s * STAGEB;
        #pragma unroll
        for (int i = 0; i < 2; i++) {
            int idx = lwi + i * 256;
            int row = idx >> 2;
            int c   = idx & 3;
            cp_async16(sstage + (uint32_t)(row * TPITCHB + c * 16),
                       gbase + (size_t)(rowoff + row) * KK + k0 + c * 8);
        }
    };

    const uint32_t aoff = (uint32_t)((wm * 32 + (lane & 15)) * TPITCHB + (lane >> 4) * 16);
    const uint32_t boff = (uint32_t)((wn * 32 + ((lane >> 4) << 3) + (lane & 7)) * TPITCHB
                                     + ((lane >> 3) & 1) * 16);

    float acc[2][4][4];
    #pragma unroll
    for (int mt = 0; mt < 2; mt++)
        #pragma unroll
        for (int nt = 0; nt < 4; nt++)
            #pragma unroll
            for (int r = 0; r < 4; r++) acc[mt][nt][r] = 0.f;

    load_stage(0, 0); CP_COMMIT();
    load_stage(1, 1); CP_COMMIT();
    load_stage(2, 2); CP_COMMIT();

    for (int t = 0; t < NCHUNK; t++) {
        const int s = t & 3;
        CP_WAIT2();
        __syncthreads();

        if (t + 3 < NCHUNK) load_stage(t + 3, (t + 3) & 3);
        CP_COMMIT();

        const uint32_t stA = sb + s * STAGEB;
        const uint32_t stB = stA + TILEB;

        #pragma unroll
        for (int ks = 0; ks < 2; ks++) {
            uint32_t ah[2][4], bh[4][2];
            #pragma unroll
            for (int mt = 0; mt < 2; mt++)
                LDSM4(ah[mt][0], ah[mt][1], ah[mt][2], ah[mt][3],
                      stA + aoff + mt * (16 * TPITCHB) + ks * 32);
            #pragma unroll
            for (int bt = 0; bt < 2; bt++) {
                uint32_t r0, r1, r2, r3;
                LDSM4(r0, r1, r2, r3, stB + boff + bt * (16 * TPITCHB) + ks * 32);
                bh[bt * 2][0] = r0; bh[bt * 2][1] = r1;
                bh[bt * 2 + 1][0] = r2; bh[bt * 2 + 1][1] = r3;
            }
            #pragma unroll
            for (int mt = 0; mt < 2; mt++)
                #pragma unroll
                for (int nt = 0; nt < 4; nt++)
                    MMAF16(acc[mt][nt], ah[mt], bh[nt]);
        }
    }

    // ---- epilogue ----
    __nv_bfloat16* Yhi = (z == 0) ? Y0hi : (z == 1) ? Y1hi : Y2hi;
    __nv_bfloat16* Ylo = (z == 0) ? Y0lo : (z == 1) ? Y1lo : Y2lo;
    #pragma unroll
    for (int mt = 0; mt < 2; mt++) {
        const int mrow = m0 + wm * 32 + mt * 16 + (lane >> 2);
        #pragma unroll
        for (int nt = 0; nt < 4; nt++) {
            const int ncl = wn * 32 + nt * 8 + (lane & 3) * 2;
            float a0 = acc[mt][nt][0], a1 = acc[mt][nt][1];
            float a2 = acc[mt][nt][2], a3 = acc[mt][nt][3];
            if (qkv) {
                const int b = mrow >> 11;
                const int srow = mrow & 2047;
                const int h = n0 >> 7;
                size_t idx0 = (((size_t)(b * HH + h) * SS) + srow) * HD + ncl;
                size_t idx1 = idx0 + (size_t)8 * HD;
                __nv_bfloat16 h0 = __float2bfloat16(a0), h1 = __float2bfloat16(a1);
                __nv_bfloat16 h2 = __float2bfloat16(a2), h3 = __float2bfloat16(a3);
                *(uint32_t*)(Yhi + idx0) = packbf(a0, a1);
                *(uint32_t*)(Yhi + idx1) = packbf(a2, a3);
                *(uint32_t*)(Ylo + idx0) =
                    packbf(a0 - __bfloat162float(h0), a1 - __bfloat162float(h1));
                *(uint32_t*)(Ylo + idx1) =
                    packbf(a2 - __bfloat162float(h2), a3 - __bfloat162float(h3));
            } else {
                float* basep = Yf + (size_t)mrow * DD + n0 + ncl;
                *(float2*)basep = make_float2(a0, a1);
                *(float2*)(basep + (size_t)8 * DD) = make_float2(a2, a3);
            }
        }
    }
}

// ---------------------------------------------------------------------------
// Flash attention (Round-9): BQ=128, BKV=64, 8 warps, warp-local softmax,
// P in registers, split-bf16 3-term math. Epilogue emits fp16 for the
// output projection.
// ---------------------------------------------------------------------------
#define APITCH    272
#define AQ_TILE   (128 * APITCH)     // 34816 (one of hi/lo)
#define AKV_TILE  (64 * APITCH)      // 17408
#define AOFF_Q    0
#define AOFF_STAGE (2 * AQ_TILE)     // 69632
#define AKV_STAGE (4 * AKV_TILE)     // 69632
#define ATT_SMEM  (AOFF_STAGE + 2 * AKV_STAGE)   // 208896
#define NKV       (SS / 64)

__global__ __launch_bounds__(256, 1) void attn_hmma(
    const __nv_bfloat16* __restrict__ Qhi_g, const __nv_bfloat16* __restrict__ Qlo_g,
    const __nv_bfloat16* __restrict__ Khi_g, const __nv_bfloat16* __restrict__ Klo_g,
    const __nv_bfloat16* __restrict__ Vhi_g, const __nv_bfloat16* __restrict__ Vlo_g,
    __half* __restrict__ A16)
{
    extern __shared__ char smem[];
    const uint32_t sb = smem_to_u32(smem);

    const int tid  = threadIdx.x;
    const int wid  = tid >> 5;     // 0..7: q-row band of 16
    const int lane = tid & 31;
    const int q0   = blockIdx.x * 128;
    const int bh   = blockIdx.y;
    const size_t bhoff = (size_t)bh * SS * HD;

    // ---- load Q (hi,lo): 128 rows x 128 cols ----
    {
        const __nv_bfloat16* qh = Qhi_g + bhoff + (size_t)q0 * HD;
        const __nv_bfloat16* ql = Qlo_g + bhoff + (size_t)q0 * HD;
        for (int i = tid; i < 128 * 16; i += 256) {
            int r = i >> 4, c = i & 15;
            *(uint4*)(smem + AOFF_Q + r * APITCH + c * 16) =
                *(const uint4*)(qh + (size_t)r * HD + c * 8);
            *(uint4*)(smem + AOFF_Q + AQ_TILE + r * APITCH + c * 16) =
                *(const uint4*)(ql + (size_t)r * HD + c * 8);
        }
    }

    const __nv_bfloat16* kvbase[4] = {Khi_g + bhoff, Klo_g + bhoff,
                                      Vhi_g + bhoff, Vlo_g + bhoff};
    auto load_kv = [&](int chunk, int s) {
        const uint32_t sstage = sb + AOFF_STAGE + s * AKV_STAGE;
        #pragma unroll
        for (int t = 0; t < 16; t++) {
            int tile = t >> 2;
            int r = (16 * t + (tid >> 4)) & 63;
            int c = tid & 15;
            cp_async16(sstage + tile * AKV_TILE + r * APITCH + c * 16,
                       kvbase[tile] + (size_t)(chunk * 64 + r) * HD + c * 8);
        }
    };

    const uint32_t qBase = sb + AOFF_Q
        + (wid * 16 + (lane & 15)) * APITCH + (lane >> 4) * 16;
    const uint32_t kFragOff = (uint32_t)((((lane >> 4) << 3) + (lane & 7)) * APITCH
                                         + ((lane >> 3) & 1) * 16);
    const int vRow = ((lane >> 3) & 1) * 8 + (lane & 7);
    const uint32_t vColBase = (uint32_t)((lane >> 4) * 16);

    float of[16][4];
    #pragma unroll
    for (int i = 0; i < 16; i++)
        #pragma unroll
        for (int j = 0; j < 4; j++) of[i][j] = 0.f;
    float m0 = -1e30f, m1 = -1e30f, l0 = 0.f, l1 = 0.f;

    const float sm_scale = 0.08838834764831843f;  // 1/sqrt(128)

    load_kv(0, 0); CP_COMMIT();
    load_kv(1, 1); CP_COMMIT();

    for (int t = 0; t < NKV; t++) {
        const int s = t & 1;
        CP_WAIT1();
        __syncthreads();

        const uint32_t sK  = sb + AOFF_STAGE + s * AKV_STAGE;
        const uint32_t sKl = sK + AKV_TILE;
        const uint32_t sV  = sK + 2 * AKV_TILE;
        const uint32_t sVl = sK + 3 * AKV_TILE;

        // ---- S = Q K^T over full kv width (8 n8 tiles) ----
        float sf[8][4];
        #pragma unroll
        for (int nt = 0; nt < 8; nt++)
            #pragma unroll
            for (int j = 0; j < 4; j++) sf[nt][j] = 0.f;

        #pragma unroll
        for (int ks = 0; ks < 8; ks++) {
            uint32_t qh[4], ql[4], kh[8][2], kl[8][2];
            LDSM4(qh[0], qh[1], qh[2], qh[3], qBase + ks * 32);
            LDSM4(ql[0], ql[1], ql[2], ql[3], qBase + AQ_TILE + ks * 32);
            #pragma unroll
            for (int nk = 0; nk < 4; nk++) {
                uint32_t r0, r1, r2, r3;
                LDSM4(r0, r1, r2, r3, sK + nk * (16 * APITCH) + kFragOff + ks * 32);
                kh[nk * 2][0] = r0; kh[nk * 2][1] = r1;
                kh[nk * 2 + 1][0] = r2; kh[nk * 2 + 1][1] = r3;
                LDSM4(r0, r1, r2, r3, sKl + nk * (16 * APITCH) + kFragOff + ks * 32);
                kl[nk * 2][0] = r0; kl[nk * 2][1] = r1;
                kl[nk * 2 + 1][0] = r2; kl[nk * 2 + 1][1] = r3;
            }
            #pragma unroll
            for (int nt = 0; nt < 8; nt++) {
                MMA16816(sf[nt], qh, kh[nt]);
                MMA16816(sf[nt], qh, kl[nt]);
                MMA16816(sf[nt], ql, kh[nt]);
            }
        }

        // ---- warp-local online softmax ----
        #pragma unroll
        for (int nt = 0; nt < 8; nt++)
            #pragma unroll
            for (int j = 0; j < 4; j++) sf[nt][j] *= sm_scale;

        float mx0 = -1e30f, mx1 = -1e30f;
        #pragma unroll
        for (int nt = 0; nt < 8; nt++) {
            mx0 = fmaxf(mx0, fmaxf(sf[nt][0], sf[nt][1]));
            mx1 = fmaxf(mx1, fmaxf(sf[nt][2], sf[nt][3]));
        }
        mx0 = fmaxf(mx0, __shfl_xor_sync(0xffffffffu, mx0, 1));
        mx0 = fmaxf(mx0, __shfl_xor_sync(0xffffffffu, mx0, 2));
        mx1 = fmaxf(mx1, __shfl_xor_sync(0xffffffffu, mx1, 1));
        mx1 = fmaxf(mx1, __shfl_xor_sync(0xffffffffu, mx1, 2));

        const float mn0 = fmaxf(m0, mx0);
        const float mn1 = fmaxf(m1, mx1);
        const float al0 = __expf(m0 - mn0);
        const float al1 = __expf(m1 - mn1);

        float sum0 = 0.f, sum1 = 0.f;
        #pragma unroll
        for (int nt = 0; nt < 8; nt++) {
            sf[nt][0] = __expf(sf[nt][0] - mn0);
            sf[nt][1] = __expf(sf[nt][1] - mn0);
            sf[nt][2] = __expf(sf[nt][2] - mn1);
            sf[nt][3] = __expf(sf[nt][3] - mn1);
            sum0 += sf[nt][0] + sf[nt][1];
            sum1 += sf[nt][2] + sf[nt][3];
        }
        sum0 += __shfl_xor_sync(0xffffffffu, sum0, 1);
        sum0 += __shfl_xor_sync(0xffffffffu, sum0, 2);
        sum1 += __shfl_xor_sync(0xffffffffu, sum1, 1);
        sum1 += __shfl_xor_sync(0xffffffffu, sum1, 2);

        l0 = l0 * al0 + sum0;
        l1 = l1 * al1 + sum1;
        m0 = mn0; m1 = mn1;

        #pragma unroll
        for (int nt = 0; nt < 16; nt++) {
            of[nt][0] *= al0; of[nt][1] *= al0;
            of[nt][2] *= al1; of[nt][3] *= al1;
        }

        // ---- O += P V  (P from registers: S frags -> A frags) ----
        #pragma unroll
        for (int ks = 0; ks < 4; ks++) {
            const int t0 = 2 * ks, t1 = 2 * ks + 1;
            uint32_t ph[4], pl[4];
            ph[0] = packbf(sf[t0][0], sf[t0][1]);
            ph[1] = packbf(sf[t0][2], sf[t0][3]);
            ph[2] = packbf(sf[t1][0], sf[t1][1]);
            ph[3] = packbf(sf[t1][2], sf[t1][3]);
            {
                float d00 = sf[t0][0] - __bfloat162float(__float2bfloat16(sf[t0][0]));
                float d01 = sf[t0][1] - __bfloat162float(__float2bfloat16(sf[t0][1]));
                float d02 = sf[t0][2] - __bfloat162float(__float2bfloat16(sf[t0][2]));
                float d03 = sf[t0][3] - __bfloat162float(__float2bfloat16(sf[t0][3]));
                float d10 = sf[t1][0] - __bfloat162float(__float2bfloat16(sf[t1][0]));
                float d11 = sf[t1][1] - __bfloat162float(__float2bfloat16(sf[t1][1]));
                float d12 = sf[t1][2] - __bfloat162float(__float2bfloat16(sf[t1][2]));
                float d13 = sf[t1][3] - __bfloat162float(__float2bfloat16(sf[t1][3]));
                pl[0] = packbf(d00, d01);
                pl[1] = packbf(d02, d03);
                pl[2] = packbf(d10, d11);
                pl[3] = packbf(d12, d13);
            }
            const uint32_t vro = (uint32_t)((ks * 16 + vRow) * APITCH) + vColBase;
            #pragma unroll
            for (int nt4 = 0; nt4 < 8; nt4++) {
                uint32_t r0, r1, r2, r3;
                uint32_t vh0[2], vh1[2], vl0[2], vl1[2];
                LDSM4T(r0, r1, r2, r3, sV + vro + nt4 * 32);
                vh0[0] = r0; vh0[1] = r1; vh1[0] = r2; vh1[1] = r3;
                LDSM4T(r0, r1, r2, r3, sVl + vro + nt4 * 32);
                vl0[0] = r0; vl0[1] = r1; vl1[0] = r2; vl1[1] = r3;
                MMA16816(of[nt4 * 2], ph, vh0);
                MMA16816(of[nt4 * 2], pl, vh0);
                MMA16816(of[nt4 * 2], ph, vl0);
                MMA16816(of[nt4 * 2 + 1], ph, vh1);
                MMA16816(of[nt4 * 2 + 1], pl, vh1);
                MMA16816(of[nt4 * 2 + 1], ph, vl1);
            }
        }

        __syncthreads();
        if (t + 2 < NKV) { load_kv(t + 2, s); CP_COMMIT(); }
    }

    // ---- epilogue: O/l -> fp16 at [b, s, d] ----
    const int b = bh >> 4;
    const int h = bh & 15;
    const float inv0 = 1.0f / l0;
    const float inv1 = 1.0f / l1;
    const int s0 = q0 + wid * 16 + (lane >> 2);
    #pragma unroll
    for (int nt = 0; nt < 16; nt++) {
        const int d = h * 128 + nt * 8 + (lane & 3) * 2;
        size_t idx0 = ((size_t)(b * SS + s0)) * DD + d;
        size_t idx1 = idx0 + (size_t)8 * DD;
        *(uint32_t*)(A16 + idx0) =
            packh2(__float2half(of[nt][0] * inv0), __float2half(of[nt][1] * inv0));
        *(uint32_t*)(A16 + idx1) =
            packh2(__float2half(of[nt][2] * inv1), __float2half(of[nt][3] * inv1));
    }
}

// ---------------------------------------------------------------------------
extern "C" void kernel_launch(void* const* d_in, const int* in_sizes, int n_in,
                              void* d_out, int out_size)
{
    const float* x  = (const float*)d_in[0];
    const float* Wq = (const float*)d_in[1];
    const float* Wk = (const float*)d_in[2];
    const float* Wv = (const float*)d_in[3];
    const float* Wo = (const float*)d_in[4];

    __half *x16, *w16, *a16;
    __nv_bfloat16 *qhi, *qlo, *khi, *klo, *vhi, *vlo;
    cudaGetSymbolAddress((void**)&x16, g_x16);
    cudaGetSymbolAddress((void**)&w16, g_w16);
    cudaGetSymbolAddress((void**)&a16, g_a16);
    cudaGetSymbolAddress((void**)&qhi, g_qhi);
    cudaGetSymbolAddress((void**)&qlo, g_qlo);
    cudaGetSymbolAddress((void**)&khi, g_khi);
    cudaGetSymbolAddress((void**)&klo, g_klo);
    cudaGetSymbolAddress((void**)&vhi, g_vhi);
    cudaGetSymbolAddress((void**)&vlo, g_vlo);

    cudaFuncSetAttribute(gemm_f16, cudaFuncAttributeMaxDynamicSharedMemorySize,
                         GSMEM_TOTAL);
    cudaFuncSetAttribute(attn_hmma, cudaFuncAttributeMaxDynamicSharedMemorySize,
                         ATT_SMEM);

    const int xn4 = (int)((size_t)MTOT * DD / 4);
    const int wn4 = (int)((size_t)DD * DD / 4);

    split_all_kernel<<<dim3((xn4 + 255) / 256, 5), 256>>>(
        x, Wq, Wk, Wv, Wo, x16, w16, xn4, wn4);

    dim3 gqkv(DD / 128, MTOT / 128, 3);
    gemm_f16<<<gqkv, 512, GSMEM_TOTAL>>>(x16, w16, nullptr,
                                         qhi, qlo, khi, klo, vhi, vlo, 1);

    attn_hmma<<<dim3(SS / 128, Bb * HH), 256, ATT_SMEM>>>(
        qhi, qlo, khi, klo, vhi, vlo, a16);

    dim3 go(DD / 128, MTOT / 128, 1);
    gemm_f16<<<go, 512, GSMEM_TOTAL>>>(a16, w16 + (size_t)3 * DD * DD,
                                       (float*)d_out,
                                       nullptr, nullptr, nullptr, nullptr,
                                       nullptr, nullptr, 0);
}

// round 11
// speedup vs baseline: 2.6916x; 1.4023x over previous
#include <cuda_runtime.h>
#include <cuda_fp16.h>
#include <stdint.h>
#include <math.h>

// Problem constants
#define Bb   2
#define SS   2048
#define DD   2048
#define HH   16
#define HD   128
#define MTOT 4096   // Bb*SS
#define KK   2048

// ---------------------------------------------------------------------------
// Scratch (device globals: allocation-free rule)
// ---------------------------------------------------------------------------
__device__ __half g_x16[(size_t)MTOT * DD];
__device__ __half g_w16[(size_t)4 * DD * DD];   // Wq,Wk,Wv,Wo (fp16)
__device__ __half g_q16[(size_t)Bb * HH * SS * HD];  // [b,h,s,hd]
__device__ __half g_k16[(size_t)Bb * HH * SS * HD];
__device__ __half g_v16[(size_t)Bb * HH * SS * HD];
__device__ __half g_a16[(size_t)MTOT * DD];     // attn out [b,s,d]

// ---------------------------------------------------------------------------
// PTX helpers (family-safe: sm_80-class instructions only)
// ---------------------------------------------------------------------------
__device__ __forceinline__ uint32_t smem_to_u32(const void* p) {
    uint32_t a;
    asm("{ .reg .u64 t; cvta.to.shared.u64 t, %1; cvt.u32.u64 %0, t; }"
        : "=r"(a) : "l"(p));
    return a;
}

__device__ __forceinline__ void cp_async16(uint32_t saddr, const void* gaddr) {
    asm volatile("cp.async.cg.shared.global [%0], [%1], 16;"
                 :: "r"(saddr), "l"(gaddr) : "memory");
}
#define CP_COMMIT() asm volatile("cp.async.commit_group;" ::: "memory")
#define CP_WAIT1()  asm volatile("cp.async.wait_group 1;" ::: "memory")
#define CP_WAIT2()  asm volatile("cp.async.wait_group 2;" ::: "memory")

#define LDSM4(r0, r1, r2, r3, addr) \
    asm volatile("ldmatrix.sync.aligned.m8n8.x4.shared.b16 {%0,%1,%2,%3}, [%4];" \
                 : "=r"(r0), "=r"(r1), "=r"(r2), "=r"(r3) : "r"(addr))

#define LDSM4T(r0, r1, r2, r3, addr) \
    asm volatile("ldmatrix.sync.aligned.m8n8.x4.trans.shared.b16 {%0,%1,%2,%3}, [%4];" \
                 : "=r"(r0), "=r"(r1), "=r"(r2), "=r"(r3) : "r"(addr))

#define MMAF16(d, a, b) \
    asm volatile("mma.sync.aligned.m16n8k16.row.col.f32.f16.f16.f32 " \
                 "{%0,%1,%2,%3}, {%4,%5,%6,%7}, {%8,%9}, {%0,%1,%2,%3};" \
                 : "+f"((d)[0]), "+f"((d)[1]), "+f"((d)[2]), "+f"((d)[3]) \
                 : "r"((a)[0]), "r"((a)[1]), "r"((a)[2]), "r"((a)[3]), \
                   "r"((b)[0]), "r"((b)[1]))

__device__ __forceinline__ uint32_t packh2(__half a, __half b) {
    __half2 t = __halves2half2(a, b);
    return *(uint32_t*)&t;
}
__device__ __forceinline__ uint32_t packh2f(float a, float b) {
    __half2 t = __floats2half2_rn(a, b);
    return *(uint32_t*)&t;
}

// ---------------------------------------------------------------------------
// Fused convert: x and all 4 weights -> fp16.  blockIdx.y: 0 -> x, 1..4 -> W.
// ---------------------------------------------------------------------------
__global__ __launch_bounds__(256) void split_all_kernel(
    const float* __restrict__ x,  const float* __restrict__ Wq,
    const float* __restrict__ Wk, const float* __restrict__ Wv,
    const float* __restrict__ Wo,
    __half* __restrict__ x16, __half* __restrict__ w16,
    int xn4, int wn4)
{
    const int y = blockIdx.y;
    const float* in;
    __half* h16;
    int n4;
    if (y == 0) { in = x; h16 = x16; n4 = xn4; }
    else {
        const float* ws[4] = {Wq, Wk, Wv, Wo};
        in = ws[y - 1];
        h16 = w16 + (size_t)(y - 1) * DD * DD;
        n4 = wn4;
    }
    int i = blockIdx.x * blockDim.x + threadIdx.x;
    if (i >= n4) return;
    float4 v = ((const float4*)in)[i];
    ((uint32_t*)h16)[2 * i + 0] = packh2f(v.x, v.y);
    ((uint32_t*)h16)[2 * i + 1] = packh2f(v.z, v.w);
}

// ---------------------------------------------------------------------------
// fp16 single-term GEMM:  Y[m,n] = sum_k X16[m,k] * W16[n,k]
// 512 threads / 16 warps, warp tile 32x32, CTA 128x128, BK=32,
// 4-stage cp.async, one barrier per chunk.
// qkv==1: gridDim.z selects weight slice; fp16 Q/K/V out in [b,h,s,hd].
// qkv==0: fp32 output Yf.
// ---------------------------------------------------------------------------
#define TPITCHB  80
#define TILEB    10240         // 128 * 80
#define STAGEB   20480         // 2 tiles (X, W)
#define NSTAGE   4
#define GSMEM_TOTAL (NSTAGE * STAGEB)   // 81920
#define NCHUNK   (KK / 32)

__global__ __launch_bounds__(512, 1) void gemm_f16(
    const __half* __restrict__ X16, const __half* __restrict__ W16Base,
    float* __restrict__ Yf,
    __half* __restrict__ Y0, __half* __restrict__ Y1, __half* __restrict__ Y2,
    int qkv)
{
    extern __shared__ char smem[];
    const uint32_t sb = smem_to_u32(smem);

    const int tid  = threadIdx.x;
    const int wid  = tid >> 5;
    const int lane = tid & 31;
    const int wm   = wid >> 2;    // 0..3
    const int wn   = wid & 3;     // 0..3
    const int m0   = blockIdx.y * 128;
    const int n0   = blockIdx.x * 128;
    const int z    = blockIdx.z;

    const __half* W16 = W16Base + (size_t)z * DD * DD;

    // loader: 2 groups of 256 threads (tile 0: X, tile 1: W)
    const int ltile = tid >> 8;
    const int lwi   = tid & 255;
    const __half* gbase = (ltile == 0) ? X16 : W16;
    const int rowoff = (ltile == 0) ? m0 : n0;
    const uint32_t stile = sb + ltile * TILEB;

    auto load_stage = [&](int chunk, int s) {
        const int k0 = chunk * 32;
        const uint32_t sstage = stile + s * STAGEB;
        #pragma unroll
        for (int i = 0; i < 2; i++) {
            int idx = lwi + i * 256;
            int row = idx >> 2;
            int c   = idx & 3;
            cp_async16(sstage + (uint32_t)(row * TPITCHB + c * 16),
                       gbase + (size_t)(rowoff + row) * KK + k0 + c * 8);
        }
    };

    const uint32_t aoff = (uint32_t)((wm * 32 + (lane & 15)) * TPITCHB + (lane >> 4) * 16);
    const uint32_t boff = (uint32_t)((wn * 32 + ((lane >> 4) << 3) + (lane & 7)) * TPITCHB
                                     + ((lane >> 3) & 1) * 16);

    float acc[2][4][4];
    #pragma unroll
    for (int mt = 0; mt < 2; mt++)
        #pragma unroll
        for (int nt = 0; nt < 4; nt++)
            #pragma unroll
            for (int r = 0; r < 4; r++) acc[mt][nt][r] = 0.f;

    load_stage(0, 0); CP_COMMIT();
    load_stage(1, 1); CP_COMMIT();
    load_stage(2, 2); CP_COMMIT();

    for (int t = 0; t < NCHUNK; t++) {
        const int s = t & 3;
        CP_WAIT2();
        __syncthreads();

        if (t + 3 < NCHUNK) load_stage(t + 3, (t + 3) & 3);
        CP_COMMIT();

        const uint32_t stA = sb + s * STAGEB;
        const uint32_t stB = stA + TILEB;

        #pragma unroll
        for (int ks = 0; ks < 2; ks++) {
            uint32_t ah[2][4], bh[4][2];
            #pragma unroll
            for (int mt = 0; mt < 2; mt++)
                LDSM4(ah[mt][0], ah[mt][1], ah[mt][2], ah[mt][3],
                      stA + aoff + mt * (16 * TPITCHB) + ks * 32);
            #pragma unroll
            for (int bt = 0; bt < 2; bt++) {
                uint32_t r0, r1, r2, r3;
                LDSM4(r0, r1, r2, r3, stB + boff + bt * (16 * TPITCHB) + ks * 32);
                bh[bt * 2][0] = r0; bh[bt * 2][1] = r1;
                bh[bt * 2 + 1][0] = r2; bh[bt * 2 + 1][1] = r3;
            }
            #pragma unroll
            for (int mt = 0; mt < 2; mt++)
                #pragma unroll
                for (int nt = 0; nt < 4; nt++)
                    MMAF16(acc[mt][nt], ah[mt], bh[nt]);
        }
    }

    // ---- epilogue ----
    __half* Yh = (z == 0) ? Y0 : (z == 1) ? Y1 : Y2;
    #pragma unroll
    for (int mt = 0; mt < 2; mt++) {
        const int mrow = m0 + wm * 32 + mt * 16 + (lane >> 2);
        #pragma unroll
        for (int nt = 0; nt < 4; nt++) {
            const int ncl = wn * 32 + nt * 8 + (lane & 3) * 2;
            float a0 = acc[mt][nt][0], a1 = acc[mt][nt][1];
            float a2 = acc[mt][nt][2], a3 = acc[mt][nt][3];
            if (qkv) {
                const int b = mrow >> 11;
                const int srow = mrow & 2047;
                const int h = n0 >> 7;
                size_t idx0 = (((size_t)(b * HH + h) * SS) + srow) * HD + ncl;
                size_t idx1 = idx0 + (size_t)8 * HD;
                *(uint32_t*)(Yh + idx0) = packh2f(a0, a1);
                *(uint32_t*)(Yh + idx1) = packh2f(a2, a3);
            } else {
                float* basep = Yf + (size_t)mrow * DD + n0 + ncl;
                *(float2*)basep = make_float2(a0, a1);
                *(float2*)(basep + (size_t)8 * DD) = make_float2(a2, a3);
            }
        }
    }
}

// ---------------------------------------------------------------------------
// fp16 flash attention: BQ=128, BKV=64, 8 warps, each warp owns 16 full
// q-rows; warp-local softmax; P in registers as fp16.
// SMEM: Q tile (128x272B) + 2-stage {K|V} (2x17408B each).
// ---------------------------------------------------------------------------
#define APITCH    272
#define AQ_TILE   (128 * APITCH)     // 34816
#define AKV_TILE  (64 * APITCH)      // 17408
#define AKV_STAGE (2 * AKV_TILE)     // 34816
#define AOFF_STAGE AQ_TILE
#define ATT_SMEM  (AQ_TILE + 2 * AKV_STAGE)   // 104448
#define NKV       (SS / 64)

__global__ __launch_bounds__(256, 1) void attn_f16(
    const __half* __restrict__ Q16, const __half* __restrict__ K16,
    const __half* __restrict__ V16, __half* __restrict__ A16)
{
    extern __shared__ char smem[];
    const uint32_t sb = smem_to_u32(smem);

    const int tid  = threadIdx.x;
    const int wid  = tid >> 5;     // 0..7: q-row band of 16
    const int lane = tid & 31;
    const int q0   = blockIdx.x * 128;
    const int bh   = blockIdx.y;
    const size_t bhoff = (size_t)bh * SS * HD;

    // ---- load Q: 128 rows x 128 cols fp16 ----
    {
        const __half* qp = Q16 + bhoff + (size_t)q0 * HD;
        for (int i = tid; i < 128 * 16; i += 256) {
            int r = i >> 4, c = i & 15;
            *(uint4*)(smem + r * APITCH + c * 16) =
                *(const uint4*)(qp + (size_t)r * HD + c * 8);
        }
    }

    const __half* kvbase[2] = {K16 + bhoff, V16 + bhoff};
    auto load_kv = [&](int chunk, int s) {
        const uint32_t sstage = sb + AOFF_STAGE + s * AKV_STAGE;
        #pragma unroll
        for (int t = 0; t < 8; t++) {
            int tile = t >> 2;
            int r = (16 * t + (tid >> 4)) & 63;
            int c = tid & 15;
            cp_async16(sstage + tile * AKV_TILE + r * APITCH + c * 16,
                       kvbase[tile] + (size_t)(chunk * 64 + r) * HD + c * 8);
        }
    };

    const uint32_t qBase = sb + (wid * 16 + (lane & 15)) * APITCH + (lane >> 4) * 16;
    const uint32_t kFragOff = (uint32_t)((((lane >> 4) << 3) + (lane & 7)) * APITCH
                                         + ((lane >> 3) & 1) * 16);
    const int vRow = ((lane >> 3) & 1) * 8 + (lane & 7);
    const uint32_t vColBase = (uint32_t)((lane >> 4) * 16);

    float of[16][4];
    #pragma unroll
    for (int i = 0; i < 16; i++)
        #pragma unroll
        for (int j = 0; j < 4; j++) of[i][j] = 0.f;
    float m0 = -1e30f, m1 = -1e30f, l0 = 0.f, l1 = 0.f;

    const float sm_scale = 0.08838834764831843f;  // 1/sqrt(128)

    load_kv(0, 0); CP_COMMIT();
    load_kv(1, 1); CP_COMMIT();

    for (int t = 0; t < NKV; t++) {
        const int s = t & 1;
        CP_WAIT1();
        __syncthreads();   // stage t resident (+ Q on first iter)

        const uint32_t sK = sb + AOFF_STAGE + s * AKV_STAGE;
        const uint32_t sV = sK + AKV_TILE;

        // ---- S = Q K^T over full kv width (8 n8 tiles) ----
        float sf[8][4];
        #pragma unroll
        for (int nt = 0; nt < 8; nt++)
            #pragma unroll
            for (int j = 0; j < 4; j++) sf[nt][j] = 0.f;

        #pragma unroll
        for (int ks = 0; ks < 8; ks++) {
            uint32_t qh[4], kh[8][2];
            LDSM4(qh[0], qh[1], qh[2], qh[3], qBase + ks * 32);
            #pragma unroll
            for (int nk = 0; nk < 4; nk++) {
                uint32_t r0, r1, r2, r3;
                LDSM4(r0, r1, r2, r3, sK + nk * (16 * APITCH) + kFragOff + ks * 32);
                kh[nk * 2][0] = r0; kh[nk * 2][1] = r1;
                kh[nk * 2 + 1][0] = r2; kh[nk * 2 + 1][1] = r3;
            }
            #pragma unroll
            for (int nt = 0; nt < 8; nt++)
                MMAF16(sf[nt], qh, kh[nt]);
        }

        // ---- warp-local online softmax (rows lane>>2, lane>>2 + 8) ----
        #pragma unroll
        for (int nt = 0; nt < 8; nt++)
            #pragma unroll
            for (int j = 0; j < 4; j++) sf[nt][j] *= sm_scale;

        float mx0 = -1e30f, mx1 = -1e30f;
        #pragma unroll
        for (int nt = 0; nt < 8; nt++) {
            mx0 = fmaxf(mx0, fmaxf(sf[nt][0], sf[nt][1]));
            mx1 = fmaxf(mx1, fmaxf(sf[nt][2], sf[nt][3]));
        }
        mx0 = fmaxf(mx0, __shfl_xor_sync(0xffffffffu, mx0, 1));
        mx0 = fmaxf(mx0, __shfl_xor_sync(0xffffffffu, mx0, 2));
        mx1 = fmaxf(mx1, __shfl_xor_sync(0xffffffffu, mx1, 1));
        mx1 = fmaxf(mx1, __shfl_xor_sync(0xffffffffu, mx1, 2));

        const float mn0 = fmaxf(m0, mx0);
        const float mn1 = fmaxf(m1, mx1);
        const float al0 = __expf(m0 - mn0);
        const float al1 = __expf(m1 - mn1);

        float sum0 = 0.f, sum1 = 0.f;
        #pragma unroll
        for (int nt = 0; nt < 8; nt++) {
            sf[nt][0] = __expf(sf[nt][0] - mn0);
            sf[nt][1] = __expf(sf[nt][1] - mn0);
            sf[nt][2] = __expf(sf[nt][2] - mn1);
            sf[nt][3] = __expf(sf[nt][3] - mn1);
            sum0 += sf[nt][0] + sf[nt][1];
            sum1 += sf[nt][2] + sf[nt][3];
        }
        sum0 += __shfl_xor_sync(0xffffffffu, sum0, 1);
        sum0 += __shfl_xor_sync(0xffffffffu, sum0, 2);
        sum1 += __shfl_xor_sync(0xffffffffu, sum1, 1);
        sum1 += __shfl_xor_sync(0xffffffffu, sum1, 2);

        l0 = l0 * al0 + sum0;
        l1 = l1 * al1 + sum1;
        m0 = mn0; m1 = mn1;

        #pragma unroll
        for (int nt = 0; nt < 16; nt++) {
            of[nt][0] *= al0; of[nt][1] *= al0;
            of[nt][2] *= al1; of[nt][3] *= al1;
        }

        // ---- O += P V  (P fp16 from registers) ----
        #pragma unroll
        for (int ks = 0; ks < 4; ks++) {
            const int t0 = 2 * ks, t1 = 2 * ks + 1;
            uint32_t ph[4];
            ph[0] = packh2f(sf[t0][0], sf[t0][1]);
            ph[1] = packh2f(sf[t0][2], sf[t0][3]);
            ph[2] = packh2f(sf[t1][0], sf[t1][1]);
            ph[3] = packh2f(sf[t1][2], sf[t1][3]);
            const uint32_t vro = (uint32_t)((ks * 16 + vRow) * APITCH) + vColBase;
            #pragma unroll
            for (int nt4 = 0; nt4 < 8; nt4++) {
                uint32_t r0, r1, r2, r3;
                uint32_t vh0[2], vh1[2];
                LDSM4T(r0, r1, r2, r3, sV + vro + nt4 * 32);
                vh0[0] = r0; vh0[1] = r1; vh1[0] = r2; vh1[1] = r3;
                MMAF16(of[nt4 * 2], ph, vh0);
                MMAF16(of[nt4 * 2 + 1], ph, vh1);
            }
        }

        __syncthreads();   // all reads of stage s done before overwrite
        if (t + 2 < NKV) { load_kv(t + 2, s); CP_COMMIT(); }
    }

    // ---- epilogue: O/l -> fp16 at [b, s, d] ----
    const int b = bh >> 4;
    const int h = bh & 15;
    const float inv0 = 1.0f / l0;
    const float inv1 = 1.0f / l1;
    const int s0 = q0 + wid * 16 + (lane >> 2);
    #pragma unroll
    for (int nt = 0; nt < 16; nt++) {
        const int d = h * 128 + nt * 8 + (lane & 3) * 2;
        size_t idx0 = ((size_t)(b * SS + s0)) * DD + d;
        size_t idx1 = idx0 + (size_t)8 * DD;
        *(uint32_t*)(A16 + idx0) = packh2f(of[nt][0] * inv0, of[nt][1] * inv0);
        *(uint32_t*)(A16 + idx1) = packh2f(of[nt][2] * inv1, of[nt][3] * inv1);
    }
}

// ---------------------------------------------------------------------------
extern "C" void kernel_launch(void* const* d_in, const int* in_sizes, int n_in,
                              void* d_out, int out_size)
{
    const float* x  = (const float*)d_in[0];
    const float* Wq = (const float*)d_in[1];
    const float* Wk = (const float*)d_in[2];
    const float* Wv = (const float*)d_in[3];
    const float* Wo = (const float*)d_in[4];

    __half *x16, *w16, *q16, *k16, *v16, *a16;
    cudaGetSymbolAddress((void**)&x16, g_x16);
    cudaGetSymbolAddress((void**)&w16, g_w16);
    cudaGetSymbolAddress((void**)&q16, g_q16);
    cudaGetSymbolAddress((void**)&k16, g_k16);
    cudaGetSymbolAddress((void**)&v16, g_v16);
    cudaGetSymbolAddress((void**)&a16, g_a16);

    cudaFuncSetAttribute(gemm_f16, cudaFuncAttributeMaxDynamicSharedMemorySize,
                         GSMEM_TOTAL);
    cudaFuncSetAttribute(attn_f16, cudaFuncAttributeMaxDynamicSharedMemorySize,
                         ATT_SMEM);

    const int xn4 = (int)((size_t)MTOT * DD / 4);
    const int wn4 = (int)((size_t)DD * DD / 4);

    split_all_kernel<<<dim3((xn4 + 255) / 256, 5), 256>>>(
        x, Wq, Wk, Wv, Wo, x16, w16, xn4, wn4);

    dim3 gqkv(DD / 128, MTOT / 128, 3);
    gemm_f16<<<gqkv, 512, GSMEM_TOTAL>>>(x16, w16, nullptr,
                                         q16, k16, v16, 1);

    attn_f16<<<dim3(SS / 128, Bb * HH), 256, ATT_SMEM>>>(q16, k16, v16, a16);

    dim3 go(DD / 128, MTOT / 128, 1);
    gemm_f16<<<go, 512, GSMEM_TOTAL>>>(a16, w16 + (size_t)3 * DD * DD,
                                       (float*)d_out,
                                       nullptr, nullptr, nullptr, 0);
}

// round 12
// speedup vs baseline: 2.8490x; 1.0585x over previous
#include <cuda_runtime.h>
#include <cuda_fp16.h>
#include <stdint.h>
#include <math.h>

// Problem constants
#define Bb   2
#define SS   2048
#define DD   2048
#define HH   16
#define HD   128
#define MTOT 4096   // Bb*SS
#define KK   2048

// ---------------------------------------------------------------------------
// Scratch (device globals: allocation-free rule)
// ---------------------------------------------------------------------------
__device__ __half g_x16[(size_t)MTOT * DD];
__device__ __half g_w16[(size_t)4 * DD * DD];   // Wq,Wk,Wv,Wo (fp16)
__device__ __half g_q16[(size_t)Bb * HH * SS * HD];  // [b,h,s,hd]
__device__ __half g_k16[(size_t)Bb * HH * SS * HD];
__device__ __half g_v16[(size_t)Bb * HH * SS * HD];
__device__ __half g_a16[(size_t)MTOT * DD];     // attn out [b,s,d]

// ---------------------------------------------------------------------------
// PTX helpers (family-safe: sm_80-class instructions only)
// ---------------------------------------------------------------------------
__device__ __forceinline__ uint32_t smem_to_u32(const void* p) {
    uint32_t a;
    asm("{ .reg .u64 t; cvta.to.shared.u64 t, %1; cvt.u32.u64 %0, t; }"
        : "=r"(a) : "l"(p));
    return a;
}

__device__ __forceinline__ void cp_async16(uint32_t saddr, const void* gaddr) {
    asm volatile("cp.async.cg.shared.global [%0], [%1], 16;"
                 :: "r"(saddr), "l"(gaddr) : "memory");
}
#define CP_COMMIT() asm volatile("cp.async.commit_group;" ::: "memory")
#define CP_WAIT1()  asm volatile("cp.async.wait_group 1;" ::: "memory")
#define CP_WAIT2()  asm volatile("cp.async.wait_group 2;" ::: "memory")

#define LDSM4(r0, r1, r2, r3, addr) \
    asm volatile("ldmatrix.sync.aligned.m8n8.x4.shared.b16 {%0,%1,%2,%3}, [%4];" \
                 : "=r"(r0), "=r"(r1), "=r"(r2), "=r"(r3) : "r"(addr))

#define LDSM4T(r0, r1, r2, r3, addr) \
    asm volatile("ldmatrix.sync.aligned.m8n8.x4.trans.shared.b16 {%0,%1,%2,%3}, [%4];" \
                 : "=r"(r0), "=r"(r1), "=r"(r2), "=r"(r3) : "r"(addr))

#define MMAF16(d, a, b) \
    asm volatile("mma.sync.aligned.m16n8k16.row.col.f32.f16.f16.f32 " \
                 "{%0,%1,%2,%3}, {%4,%5,%6,%7}, {%8,%9}, {%0,%1,%2,%3};" \
                 : "+f"((d)[0]), "+f"((d)[1]), "+f"((d)[2]), "+f"((d)[3]) \
                 : "r"((a)[0]), "r"((a)[1]), "r"((a)[2]), "r"((a)[3]), \
                   "r"((b)[0]), "r"((b)[1]))

__device__ __forceinline__ uint32_t packh2f(float a, float b) {
    __half2 t = __floats2half2_rn(a, b);
    return *(uint32_t*)&t;
}

// ---------------------------------------------------------------------------
// Fused convert: x and all 4 weights -> fp16.  blockIdx.y: 0 -> x, 1..4 -> W.
// ---------------------------------------------------------------------------
__global__ __launch_bounds__(256) void split_all_kernel(
    const float* __restrict__ x,  const float* __restrict__ Wq,
    const float* __restrict__ Wk, const float* __restrict__ Wv,
    const float* __restrict__ Wo,
    __half* __restrict__ x16, __half* __restrict__ w16,
    int xn4, int wn4)
{
    const int y = blockIdx.y;
    const float* in;
    __half* h16;
    int n4;
    if (y == 0) { in = x; h16 = x16; n4 = xn4; }
    else {
        const float* ws[4] = {Wq, Wk, Wv, Wo};
        in = ws[y - 1];
        h16 = w16 + (size_t)(y - 1) * DD * DD;
        n4 = wn4;
    }
    int i = blockIdx.x * blockDim.x + threadIdx.x;
    if (i >= n4) return;
    float4 v = ((const float4*)in)[i];
    ((uint32_t*)h16)[2 * i + 0] = packh2f(v.x, v.y);
    ((uint32_t*)h16)[2 * i + 1] = packh2f(v.z, v.w);
}

// ---------------------------------------------------------------------------
// fp16 single-term GEMM:  Y[m,n] = sum_k X16[m,k] * W16[n,k]
// 512 threads / 16 warps, warp tile 32x32, CTA 128x128.
// BK=64 (4 k16 steps per chunk), 4-stage cp.async, one barrier per chunk.
// SMEM row: 128B data + 16B pad (pitch 144 -> conflict-free ldmatrix).
// qkv==1: gridDim.z selects weight slice; fp16 Q/K/V out in [b,h,s,hd].
// qkv==0: fp32 output Yf.
// ---------------------------------------------------------------------------
#define TPITCHB  144
#define TILEB    (128 * TPITCHB)       // 18432
#define STAGEB   (2 * TILEB)           // 36864 (X tile + W tile)
#define NSTAGE   4
#define GSMEM_TOTAL (NSTAGE * STAGEB)  // 147456
#define NCHUNK   (KK / 64)             // 32

__global__ __launch_bounds__(512, 1) void gemm_f16(
    const __half* __restrict__ X16, const __half* __restrict__ W16Base,
    float* __restrict__ Yf,
    __half* __restrict__ Y0, __half* __restrict__ Y1, __half* __restrict__ Y2,
    int qkv)
{
    extern __shared__ char smem[];
    const uint32_t sb = smem_to_u32(smem);

    const int tid  = threadIdx.x;
    const int wid  = tid >> 5;
    const int lane = tid & 31;
    const int wm   = wid >> 2;    // 0..3
    const int wn   = wid & 3;     // 0..3
    const int m0   = blockIdx.y * 128;
    const int n0   = blockIdx.x * 128;
    const int z    = blockIdx.z;

    const __half* W16 = W16Base + (size_t)z * DD * DD;

    // loader: 2 groups of 256 threads (tile 0: X, tile 1: W).
    // Per stage/tile: 128 rows x 8 segs x 16B = 1024 cp.async -> 4 per thread.
    const int ltile = tid >> 8;
    const int lwi   = tid & 255;
    const __half* gbase = (ltile == 0) ? X16 : W16;
    const int rowoff = (ltile == 0) ? m0 : n0;
    const uint32_t stile = sb + ltile * TILEB;

    auto load_stage = [&](int chunk, int s) {
        const int k0 = chunk * 64;
        const uint32_t sstage = stile + s * STAGEB;
        #pragma unroll
        for (int i = 0; i < 4; i++) {
            int idx = lwi + i * 256;
            int row = idx >> 3;
            int seg = idx & 7;
            cp_async16(sstage + (uint32_t)(row * TPITCHB + seg * 16),
                       gbase + (size_t)(rowoff + row) * KK + k0 + seg * 8);
        }
    };

    const uint32_t aoff = (uint32_t)((wm * 32 + (lane & 15)) * TPITCHB + (lane >> 4) * 16);
    const uint32_t boff = (uint32_t)((wn * 32 + ((lane >> 4) << 3) + (lane & 7)) * TPITCHB
                                     + ((lane >> 3) & 1) * 16);

    float acc[2][4][4];
    #pragma unroll
    for (int mt = 0; mt < 2; mt++)
        #pragma unroll
        for (int nt = 0; nt < 4; nt++)
            #pragma unroll
            for (int r = 0; r < 4; r++) acc[mt][nt][r] = 0.f;

    load_stage(0, 0); CP_COMMIT();
    load_stage(1, 1); CP_COMMIT();
    load_stage(2, 2); CP_COMMIT();

    for (int t = 0; t < NCHUNK; t++) {
        const int s = t & 3;
        CP_WAIT2();            // stage t resident (2 newest groups in flight)
        __syncthreads();       // reads of slot (t+3)&3 complete across CTA

        if (t + 3 < NCHUNK) load_stage(t + 3, (t + 3) & 3);
        CP_COMMIT();

        const uint32_t stA = sb + s * STAGEB;
        const uint32_t stB = stA + TILEB;

        #pragma unroll
        for (int ks = 0; ks < 4; ks++) {
            uint32_t ah[2][4], bh[4][2];
            #pragma unroll
            for (int mt = 0; mt < 2; mt++)
                LDSM4(ah[mt][0], ah[mt][1], ah[mt][2], ah[mt][3],
                      stA + aoff + mt * (16 * TPITCHB) + ks * 32);
            #pragma unroll
            for (int bt = 0; bt < 2; bt++) {
                uint32_t r0, r1, r2, r3;
                LDSM4(r0, r1, r2, r3, stB + boff + bt * (16 * TPITCHB) + ks * 32);
                bh[bt * 2][0] = r0; bh[bt * 2][1] = r1;
                bh[bt * 2 + 1][0] = r2; bh[bt * 2 + 1][1] = r3;
            }
            #pragma unroll
            for (int mt = 0; mt < 2; mt++)
                #pragma unroll
                for (int nt = 0; nt < 4; nt++)
                    MMAF16(acc[mt][nt], ah[mt], bh[nt]);
        }
    }

    // ---- epilogue ----
    __half* Yh = (z == 0) ? Y0 : (z == 1) ? Y1 : Y2;
    #pragma unroll
    for (int mt = 0; mt < 2; mt++) {
        const int mrow = m0 + wm * 32 + mt * 16 + (lane >> 2);
        #pragma unroll
        for (int nt = 0; nt < 4; nt++) {
            const int ncl = wn * 32 + nt * 8 + (lane & 3) * 2;
            float a0 = acc[mt][nt][0], a1 = acc[mt][nt][1];
            float a2 = acc[mt][nt][2], a3 = acc[mt][nt][3];
            if (qkv) {
                const int b = mrow >> 11;
                const int srow = mrow & 2047;
                const int h = n0 >> 7;
                size_t idx0 = (((size_t)(b * HH + h) * SS) + srow) * HD + ncl;
                size_t idx1 = idx0 + (size_t)8 * HD;
                *(uint32_t*)(Yh + idx0) = packh2f(a0, a1);
                *(uint32_t*)(Yh + idx1) = packh2f(a2, a3);
            } else {
                float* basep = Yf + (size_t)mrow * DD + n0 + ncl;
                *(float2*)basep = make_float2(a0, a1);
                *(float2*)(basep + (size_t)8 * DD) = make_float2(a2, a3);
            }
        }
    }
}

// ---------------------------------------------------------------------------
// fp16 flash attention (Round-11): BQ=128, BKV=64, 8 warps, warp-local
// softmax, P in registers as fp16.
// ---------------------------------------------------------------------------
#define APITCH    272
#define AQ_TILE   (128 * APITCH)     // 34816
#define AKV_TILE  (64 * APITCH)      // 17408
#define AKV_STAGE (2 * AKV_TILE)     // 34816
#define AOFF_STAGE AQ_TILE
#define ATT_SMEM  (AQ_TILE + 2 * AKV_STAGE)   // 104448
#define NKV       (SS / 64)

__global__ __launch_bounds__(256, 1) void attn_f16(
    const __half* __restrict__ Q16, const __half* __restrict__ K16,
    const __half* __restrict__ V16, __half* __restrict__ A16)
{
    extern __shared__ char smem[];
    const uint32_t sb = smem_to_u32(smem);

    const int tid  = threadIdx.x;
    const int wid  = tid >> 5;     // 0..7: q-row band of 16
    const int lane = tid & 31;
    const int q0   = blockIdx.x * 128;
    const int bh   = blockIdx.y;
    const size_t bhoff = (size_t)bh * SS * HD;

    // ---- load Q: 128 rows x 128 cols fp16 ----
    {
        const __half* qp = Q16 + bhoff + (size_t)q0 * HD;
        for (int i = tid; i < 128 * 16; i += 256) {
            int r = i >> 4, c = i & 15;
            *(uint4*)(smem + r * APITCH + c * 16) =
                *(const uint4*)(qp + (size_t)r * HD + c * 8);
        }
    }

    const __half* kvbase[2] = {K16 + bhoff, V16 + bhoff};
    auto load_kv = [&](int chunk, int s) {
        const uint32_t sstage = sb + AOFF_STAGE + s * AKV_STAGE;
        #pragma unroll
        for (int t = 0; t < 8; t++) {
            int tile = t >> 2;
            int r = (16 * t + (tid >> 4)) & 63;
            int c = tid & 15;
            cp_async16(sstage + tile * AKV_TILE + r * APITCH + c * 16,
                       kvbase[tile] + (size_t)(chunk * 64 + r) * HD + c * 8);
        }
    };

    const uint32_t qBase = sb + (wid * 16 + (lane & 15)) * APITCH + (lane >> 4) * 16;
    const uint32_t kFragOff = (uint32_t)((((lane >> 4) << 3) + (lane & 7)) * APITCH
                                         + ((lane >> 3) & 1) * 16);
    const int vRow = ((lane >> 3) & 1) * 8 + (lane & 7);
    const uint32_t vColBase = (uint32_t)((lane >> 4) * 16);

    float of[16][4];
    #pragma unroll
    for (int i = 0; i < 16; i++)
        #pragma unroll
        for (int j = 0; j < 4; j++) of[i][j] = 0.f;
    float m0 = -1e30f, m1 = -1e30f, l0 = 0.f, l1 = 0.f;

    const float sm_scale = 0.08838834764831843f;  // 1/sqrt(128)

    load_kv(0, 0); CP_COMMIT();
    load_kv(1, 1); CP_COMMIT();

    for (int t = 0; t < NKV; t++) {
        const int s = t & 1;
        CP_WAIT1();
        __syncthreads();   // stage t resident (+ Q on first iter)

        const uint32_t sK = sb + AOFF_STAGE + s * AKV_STAGE;
        const uint32_t sV = sK + AKV_TILE;

        // ---- S = Q K^T over full kv width (8 n8 tiles) ----
        float sf[8][4];
        #pragma unroll
        for (int nt = 0; nt < 8; nt++)
            #pragma unroll
            for (int j = 0; j < 4; j++) sf[nt][j] = 0.f;

        #pragma unroll
        for (int ks = 0; ks < 8; ks++) {
            uint32_t qh[4], kh[8][2];
            LDSM4(qh[0], qh[1], qh[2], qh[3], qBase + ks * 32);
            #pragma unroll
            for (int nk = 0; nk < 4; nk++) {
                uint32_t r0, r1, r2, r3;
                LDSM4(r0, r1, r2, r3, sK + nk * (16 * APITCH) + kFragOff + ks * 32);
                kh[nk * 2][0] = r0; kh[nk * 2][1] = r1;
                kh[nk * 2 + 1][0] = r2; kh[nk * 2 + 1][1] = r3;
            }
            #pragma unroll
            for (int nt = 0; nt < 8; nt++)
                MMAF16(sf[nt], qh, kh[nt]);
        }

        // ---- warp-local online softmax (rows lane>>2, lane>>2 + 8) ----
        #pragma unroll
        for (int nt = 0; nt < 8; nt++)
            #pragma unroll
            for (int j = 0; j < 4; j++) sf[nt][j] *= sm_scale;

        float mx0 = -1e30f, mx1 = -1e30f;
        #pragma unroll
        for (int nt = 0; nt < 8; nt++) {
            mx0 = fmaxf(mx0, fmaxf(sf[nt][0], sf[nt][1]));
            mx1 = fmaxf(mx1, fmaxf(sf[nt][2], sf[nt][3]));
        }
        mx0 = fmaxf(mx0, __shfl_xor_sync(0xffffffffu, mx0, 1));
        mx0 = fmaxf(mx0, __shfl_xor_sync(0xffffffffu, mx0, 2));
        mx1 = fmaxf(mx1, __shfl_xor_sync(0xffffffffu, mx1, 1));
        mx1 = fmaxf(mx1, __shfl_xor_sync(0xffffffffu, mx1, 2));

        const float mn0 = fmaxf(m0, mx0);
        const float mn1 = fmaxf(m1, mx1);
        const float al0 = __expf(m0 - mn0);
        const float al1 = __expf(m1 - mn1);

        float sum0 = 0.f, sum1 = 0.f;
        #pragma unroll
        for (int nt = 0; nt < 8; nt++) {
            sf[nt][0] = __expf(sf[nt][0] - mn0);
            sf[nt][1] = __expf(sf[nt][1] - mn0);
            sf[nt][2] = __expf(sf[nt][2] - mn1);
            sf[nt][3] = __expf(sf[nt][3] - mn1);
            sum0 += sf[nt][0] + sf[nt][1];
            sum1 += sf[nt][2] + sf[nt][3];
        }
        sum0 += __shfl_xor_sync(0xffffffffu, sum0, 1);
        sum0 += __shfl_xor_sync(0xffffffffu, sum0, 2);
        sum1 += __shfl_xor_sync(0xffffffffu, sum1, 1);
        sum1 += __shfl_xor_sync(0xffffffffu, sum1, 2);

        l0 = l0 * al0 + sum0;
        l1 = l1 * al1 + sum1;
        m0 = mn0; m1 = mn1;

        #pragma unroll
        for (int nt = 0; nt < 16; nt++) {
            of[nt][0] *= al0; of[nt][1] *= al0;
            of[nt][2] *= al1; of[nt][3] *= al1;
        }

        // ---- O += P V  (P fp16 from registers) ----
        #pragma unroll
        for (int ks = 0; ks < 4; ks++) {
            const int t0 = 2 * ks, t1 = 2 * ks + 1;
            uint32_t ph[4];
            ph[0] = packh2f(sf[t0][0], sf[t0][1]);
            ph[1] = packh2f(sf[t0][2], sf[t0][3]);
            ph[2] = packh2f(sf[t1][0], sf[t1][1]);
            ph[3] = packh2f(sf[t1][2], sf[t1][3]);
            const uint32_t vro = (uint32_t)((ks * 16 + vRow) * APITCH) + vColBase;
            #pragma unroll
            for (int nt4 = 0; nt4 < 8; nt4++) {
                uint32_t r0, r1, r2, r3;
                uint32_t vh0[2], vh1[2];
                LDSM4T(r0, r1, r2, r3, sV + vro + nt4 * 32);
                vh0[0] = r0; vh0[1] = r1; vh1[0] = r2; vh1[1] = r3;
                MMAF16(of[nt4 * 2], ph, vh0);
                MMAF16(of[nt4 * 2 + 1], ph, vh1);
            }
        }

        __syncthreads();   // all reads of stage s done before overwrite
        if (t + 2 < NKV) { load_kv(t + 2, s); CP_COMMIT(); }
    }

    // ---- epilogue: O/l -> fp16 at [b, s, d] ----
    const int b = bh >> 4;
    const int h = bh & 15;
    const float inv0 = 1.0f / l0;
    const float inv1 = 1.0f / l1;
    const int s0 = q0 + wid * 16 + (lane >> 2);
    #pragma unroll
    for (int nt = 0; nt < 16; nt++) {
        const int d = h * 128 + nt * 8 + (lane & 3) * 2;
        size_t idx0 = ((size_t)(b * SS + s0)) * DD + d;
        size_t idx1 = idx0 + (size_t)8 * DD;
        *(uint32_t*)(A16 + idx0) = packh2f(of[nt][0] * inv0, of[nt][1] * inv0);
        *(uint32_t*)(A16 + idx1) = packh2f(of[nt][2] * inv1, of[nt][3] * inv1);
    }
}

// ---------------------------------------------------------------------------
extern "C" void kernel_launch(void* const* d_in, const int* in_sizes, int n_in,
                              void* d_out, int out_size)
{
    const float* x  = (const float*)d_in[0];
    const float* Wq = (const float*)d_in[1];
    const float* Wk = (const float*)d_in[2];
    const float* Wv = (const float*)d_in[3];
    const float* Wo = (const float*)d_in[4];

    __half *x16, *w16, *q16, *k16, *v16, *a16;
    cudaGetSymbolAddress((void**)&x16, g_x16);
    cudaGetSymbolAddress((void**)&w16, g_w16);
    cudaGetSymbolAddress((void**)&q16, g_q16);
    cudaGetSymbolAddress((void**)&k16, g_k16);
    cudaGetSymbolAddress((void**)&v16, g_v16);
    cudaGetSymbolAddress((void**)&a16, g_a16);

    cudaFuncSetAttribute(gemm_f16, cudaFuncAttributeMaxDynamicSharedMemorySize,
                         GSMEM_TOTAL);
    cudaFuncSetAttribute(attn_f16, cudaFuncAttributeMaxDynamicSharedMemorySize,
                         ATT_SMEM);

    const int xn4 = (int)((size_t)MTOT * DD / 4);
    const int wn4 = (int)((size_t)DD * DD / 4);

    split_all_kernel<<<dim3((xn4 + 255) / 256, 5), 256>>>(
        x, Wq, Wk, Wv, Wo, x16, w16, xn4, wn4);

    dim3 gqkv(DD / 128, MTOT / 128, 3);
    gemm_f16<<<gqkv, 512, GSMEM_TOTAL>>>(x16, w16, nullptr,
                                         q16, k16, v16, 1);

    attn_f16<<<dim3(SS / 128, Bb * HH), 256, ATT_SMEM>>>(q16, k16, v16, a16);

    dim3 go(DD / 128, MTOT / 128, 1);
    gemm_f16<<<go, 512, GSMEM_TOTAL>>>(a16, w16 + (size_t)3 * DD * DD,
                                       (float*)d_out,
                                       nullptr, nullptr, nullptr, 0);
}